// round 1
// baseline (speedup 1.0000x reference)
#include <cuda_runtime.h>
#include <cuda_bf16.h>
#include <math.h>

// Problem constants
#define BB 8
#define NN 512
#define CC 1024
#define HH 16
#define HD 64
#define LL 6
#define FF 4096
#define OUTD 2
#define MM (BB*NN)          // 4096 rows
#define BHN (BB*HH)         // 128 batched heads

// ---------------- scratch (static device globals; no allocation) ----------------
__device__ float g_x [MM*CC];          // residual stream
__device__ float g_h [MM*CC];          // LN output / o_lin reuse
__device__ float g_t [MM*FF];          // qkv tmp (4096x3072) / FF1 out (4096x4096)
__device__ float g_t2[MM*CC];          // proj outputs before residual add
__device__ float g_q [BHN*NN*HD];
__device__ float g_k [BHN*NN*HD];
__device__ float g_vT[BHN*HD*NN];      // V transposed: [bh][hd][n]
__device__ float g_S [BHN*NN*NN];      // attention scores (134 MB)
__device__ float g_O [BHN*NN*HD];

// ---------------- f32x2 packed helpers (sm_103a dual-rate fp32) ----------------
__device__ __forceinline__ unsigned long long pack2(float x, float y) {
    unsigned long long r;
    asm("mov.b64 %0, {%1, %2};" : "=l"(r) : "f"(x), "f"(y));
    return r;
}
__device__ __forceinline__ void fma2(unsigned long long& d, unsigned long long a, unsigned long long b) {
    asm("fma.rn.f32x2 %0, %1, %2, %0;" : "+l"(d) : "l"(a), "l"(b));
}
union U64F2 { unsigned long long u; float2 f; };

// ---------------- generic NT GEMM: C[z][m][n] = sum_k A[z][m][k]*W[z][n][k] + bias[n]
// BM=128, BN_ in {128,64}, BK=16, 256 threads, per-thread 8 x (BN_/16) tile,
// register-prefetch double buffering, f32x2 inner product.
template<int BN_>
__global__ void __launch_bounds__(256, 2)
gemm_nt(const float* __restrict__ A, const float* __restrict__ W,
        const float* __restrict__ bias, float* __restrict__ C,
        int M, int Nn, int K,
        unsigned long long sAz, unsigned long long sBz, unsigned long long sCz)
{
    constexpr int TN  = BN_ / 16;       // 8 or 4
    constexpr int LDA = 128 + 4;        // keep rows 16B aligned (132*4=528, %16==0)
    constexpr int LDB = BN_ + 4;
    constexpr int AI  = 8;              // A loads per thread per tile
    constexpr int BI  = BN_ / 16;       // W loads per thread per tile

    __shared__ float As[16][LDA];
    __shared__ float Bs[16][LDB];

    const int z = blockIdx.z;
    A += (unsigned long long)z * sAz;
    W += (unsigned long long)z * sBz;
    C += (unsigned long long)z * sCz;

    const int bm = blockIdx.y * 128;
    const int bn = blockIdx.x * BN_;
    const int tid = threadIdx.x;
    const int lk = tid & 15, lr = tid >> 4;   // loader coords
    const int tx = tid & 15, ty = tid >> 4;   // compute coords

    const float* Aptr = A + (size_t)(bm + lr) * K + lk;
    const float* Wptr = W + (size_t)(bn + lr) * K + lk;

    float pa[AI], pb[BI];
#pragma unroll
    for (int i = 0; i < AI; i++) pa[i] = Aptr[(size_t)(16 * i) * K];
#pragma unroll
    for (int i = 0; i < BI; i++) pb[i] = Wptr[(size_t)(16 * i) * K];

    unsigned long long acc[8][TN / 2] = {};

    for (int k0 = 0; k0 < K; k0 += 16) {
        // commit prefetched tile to shared
#pragma unroll
        for (int i = 0; i < AI; i++) As[lk][lr + 16 * i] = pa[i];
#pragma unroll
        for (int i = 0; i < BI; i++) Bs[lk][lr + 16 * i] = pb[i];
        __syncthreads();

        if (k0 + 16 < K) {   // issue next tile's global loads (latency overlaps compute)
            Aptr += 16; Wptr += 16;
#pragma unroll
            for (int i = 0; i < AI; i++) pa[i] = Aptr[(size_t)(16 * i) * K];
#pragma unroll
            for (int i = 0; i < BI; i++) pb[i] = Wptr[(size_t)(16 * i) * K];
        }

#pragma unroll
        for (int kk = 0; kk < 16; kk++) {
            float4 a0 = *reinterpret_cast<const float4*>(&As[kk][ty * 8]);
            float4 a1 = *reinterpret_cast<const float4*>(&As[kk][ty * 8 + 4]);
            float av[8] = {a0.x, a0.y, a0.z, a0.w, a1.x, a1.y, a1.z, a1.w};
            unsigned long long bb[TN / 2];
            const unsigned long long* bp =
                reinterpret_cast<const unsigned long long*>(&Bs[kk][tx * TN]);
#pragma unroll
            for (int jp = 0; jp < TN / 2; jp++) bb[jp] = bp[jp];
#pragma unroll
            for (int i = 0; i < 8; i++) {
                unsigned long long a2 = pack2(av[i], av[i]);
#pragma unroll
                for (int jp = 0; jp < TN / 2; jp++) fma2(acc[i][jp], a2, bb[jp]);
            }
        }
        __syncthreads();
    }

    // epilogue: + bias, vectorized float2 stores
#pragma unroll
    for (int i = 0; i < 8; i++) {
        size_t mrow = (size_t)(bm + ty * 8 + i) * Nn;
#pragma unroll
        for (int jp = 0; jp < TN / 2; jp++) {
            int n = bn + tx * TN + 2 * jp;
            U64F2 u; u.u = acc[i][jp];
            float2 r = u.f;
            if (bias) { r.x += bias[n]; r.y += bias[n + 1]; }
            *reinterpret_cast<float2*>(&C[mrow + n]) = r;
        }
    }
}

// ---------------- block reduction (broadcast result to all threads) -------------
template<bool MAXRED>
__device__ __forceinline__ float blockReduce(float val) {
    __shared__ float sh[32];
    __syncthreads();   // protect sh across repeated calls
#pragma unroll
    for (int o = 16; o > 0; o >>= 1) {
        float other = __shfl_xor_sync(0xffffffffu, val, o);
        val = MAXRED ? fmaxf(val, other) : val + other;
    }
    int w = threadIdx.x >> 5, l = threadIdx.x & 31;
    if (l == 0) sh[w] = val;
    __syncthreads();
    int nw = blockDim.x >> 5;
    if (threadIdx.x < 32) {
        val = (l < nw) ? sh[l] : (MAXRED ? -3.4e38f : 0.0f);
#pragma unroll
        for (int o = 16; o > 0; o >>= 1) {
            float other = __shfl_xor_sync(0xffffffffu, val, o);
            val = MAXRED ? fmaxf(val, other) : val + other;
        }
        if (l == 0) sh[0] = val;
    }
    __syncthreads();
    return sh[0];
}

// ---------------- layernorm: one block per row, row in registers ---------------
__global__ void layernorm_k(const float* __restrict__ x, const float* __restrict__ g,
                            const float* __restrict__ b, float* __restrict__ h)
{
    int row = blockIdx.x;
    int tid = threadIdx.x;                    // 256 threads, 4 elems each
    const float* xr = x + (size_t)row * CC;
    float v[4];
#pragma unroll
    for (int i = 0; i < 4; i++) v[i] = xr[tid + 256 * i];
    float s = v[0] + v[1] + v[2] + v[3];
    s = blockReduce<false>(s);
    float mu = s * (1.0f / CC);
    float d0 = v[0] - mu, d1 = v[1] - mu, d2 = v[2] - mu, d3 = v[3] - mu;
    float s2 = d0 * d0 + d1 * d1 + d2 * d2 + d3 * d3;
    s2 = blockReduce<false>(s2);
    float inv = rsqrtf(s2 * (1.0f / CC) + 1e-6f);
    float* hr = h + (size_t)row * CC;
#pragma unroll
    for (int i = 0; i < 4; i++) {
        int c = tid + 256 * i;
        hr[c] = (v[i] - mu) * inv * g[c] + b[c];
    }
}

// ---------------- masked softmax over S rows (row len 512) ---------------------
__global__ void softmax_k(float* __restrict__ S, const int* __restrict__ mask)
{
    int r = blockIdx.x;                    // 0..BH*N-1
    int b = r >> 13;                       // r / (H*N) = r / 8192
    float* row = S + (size_t)r * NN;
    const int* mrow = mask + b * NN;
    int tid = threadIdx.x;                 // 128 threads, 4 elems each
    float v[4];
#pragma unroll
    for (int i = 0; i < 4; i++) {
        int k = tid + 128 * i;
        float t = row[k] * 0.125f;         // scale = HD^-0.5 = 1/8
        if (mrow[k] == 0) t = -1e9f;
        v[i] = t;
    }
    float m = fmaxf(fmaxf(v[0], v[1]), fmaxf(v[2], v[3]));
    m = blockReduce<true>(m);
    float e[4], s = 0.0f;
#pragma unroll
    for (int i = 0; i < 4; i++) { e[i] = expf(v[i] - m); s += e[i]; }
    s = blockReduce<false>(s);
    float inv = 1.0f / s;
#pragma unroll
    for (int i = 0; i < 4; i++) row[tid + 128 * i] = e[i] * inv;
}

// ---------------- small elementwise kernels ------------------------------------
__global__ void add_pos_k(float* __restrict__ x, const float* __restrict__ pos, int total) {
    int i = blockIdx.x * blockDim.x + threadIdx.x;
    if (i < total) x[i] += pos[i % (NN * CC)];
}
__global__ void residual_k(float* __restrict__ x, const float* __restrict__ t, int total) {
    int i = blockIdx.x * blockDim.x + threadIdx.x;
    if (i < total) x[i] += t[i];
}
__global__ void gelu_k(float* __restrict__ t, int total) {
    int i = blockIdx.x * blockDim.x + threadIdx.x;
    if (i < total) {
        float v = t[i];
        t[i] = 0.5f * v * (1.0f + erff(v * 0.70710678118654752f));
    }
}
__global__ void qkv_scatter_k(const float* __restrict__ t, float* __restrict__ q,
                              float* __restrict__ k, float* __restrict__ vT) {
    int i = blockIdx.x * blockDim.x + threadIdx.x;
    if (i >= MM * 3 * CC) return;
    int m = i / (3 * CC), c = i - m * (3 * CC);
    int which = c >> 10;          // 0=q 1=k 2=v
    int ci = c & 1023;
    int head = ci >> 6, hd = ci & 63;
    int b = m >> 9, n = m & 511;
    int bh = b * HH + head;
    float v = t[i];
    if (which == 0)      q[((size_t)bh * NN + n) * HD + hd] = v;
    else if (which == 1) k[((size_t)bh * NN + n) * HD + hd] = v;
    else                 vT[((size_t)bh * HD + hd) * NN + n] = v;
}
__global__ void o_reshape_k(const float* __restrict__ O, float* __restrict__ o_lin) {
    int i = blockIdx.x * blockDim.x + threadIdx.x;
    if (i >= BHN * NN * HD) return;
    int bh = i / (NN * HD);
    int rem = i - bh * (NN * HD);
    int n = rem >> 6, hd = rem & 63;
    int b = bh >> 4, head = bh & 15;
    o_lin[((size_t)(b * NN + n)) * CC + head * HD + hd] = O[i];
}
// final: out[m][j] = sigmoid(x[m] . Wout[j] + bout[j]); one warp per (m,j)
__global__ void final_k(const float* __restrict__ x, const float* __restrict__ Wout,
                        const float* __restrict__ bout, float* __restrict__ out) {
    int m = blockIdx.x;
    int j = threadIdx.x >> 5;
    int lane = threadIdx.x & 31;
    const float* xr = x + (size_t)m * CC;
    const float* w  = Wout + (size_t)j * CC;
    float s = 0.0f;
#pragma unroll
    for (int t = 0; t < CC / 32; t++) s += xr[lane + 32 * t] * w[lane + 32 * t];
#pragma unroll
    for (int o = 16; o > 0; o >>= 1) s += __shfl_xor_sync(0xffffffffu, s, o);
    if (lane == 0) out[m * OUTD + j] = 1.0f / (1.0f + expf(-(s + bout[j])));
}

// ---------------- driver ---------------------------------------------------------
static inline dim3 eg(int total) { return dim3((total + 255) / 256); }

extern "C" void kernel_launch(void* const* d_in, const int* in_sizes, int n_in,
                              void* d_out, int out_size)
{
    (void)in_sizes; (void)n_in; (void)out_size;
    const float* inputs = (const float*)d_in[0];
    const int*   mask   = (const int*)  d_in[1];
    const float* pos    = (const float*)d_in[2];
    const float* Wi     = (const float*)d_in[3];
    const float* bi     = (const float*)d_in[4];
    const float* ln1_g  = (const float*)d_in[5];
    const float* ln1_b  = (const float*)d_in[6];
    const float* Wqkv   = (const float*)d_in[7];
    const float* bqkv   = (const float*)d_in[8];
    const float* Wo     = (const float*)d_in[9];
    const float* bo     = (const float*)d_in[10];
    const float* ln2_g  = (const float*)d_in[11];
    const float* ln2_b  = (const float*)d_in[12];
    const float* W1     = (const float*)d_in[13];
    const float* b1     = (const float*)d_in[14];
    const float* W2     = (const float*)d_in[15];
    const float* b2     = (const float*)d_in[16];
    const float* Wout   = (const float*)d_in[17];
    const float* bout   = (const float*)d_in[18];

    float *x, *h, *t, *t2, *q, *k, *vT, *S, *O;
    cudaGetSymbolAddress((void**)&x,  g_x);
    cudaGetSymbolAddress((void**)&h,  g_h);
    cudaGetSymbolAddress((void**)&t,  g_t);
    cudaGetSymbolAddress((void**)&t2, g_t2);
    cudaGetSymbolAddress((void**)&q,  g_q);
    cudaGetSymbolAddress((void**)&k,  g_k);
    cudaGetSymbolAddress((void**)&vT, g_vT);
    cudaGetSymbolAddress((void**)&S,  g_S);
    cudaGetSymbolAddress((void**)&O,  g_O);

    const int tot_xc = MM * CC;        // 4.19M
    const int tot_qkv = MM * 3 * CC;   // 12.6M
    const int tot_ff = MM * FF;        // 16.8M
    const int tot_o = BHN * NN * HD;   // 4.19M

    // x = inputs @ Wi.T + bi ; x += pos
    gemm_nt<128><<<dim3(CC / 128, MM / 128, 1), 256>>>(inputs, Wi, bi, x, MM, CC, CC, 0, 0, 0);
    add_pos_k<<<eg(tot_xc), 256>>>(x, pos, tot_xc);

    for (int l = 0; l < LL; l++) {
        // LN1
        layernorm_k<<<MM, 256>>>(x, ln1_g + l * CC, ln1_b + l * CC, h);
        // qkv = h @ Wqkv[l].T + bqkv[l]  -> t [4096,3072]
        gemm_nt<128><<<dim3(3 * CC / 128, MM / 128, 1), 256>>>(
            h, Wqkv + (size_t)l * 3 * CC * CC, bqkv + (size_t)l * 3 * CC, t, MM, 3 * CC, CC, 0, 0, 0);
        qkv_scatter_k<<<eg(tot_qkv), 256>>>(t, q, k, vT);
        // S = q @ k.T  (batched over 128 heads)
        gemm_nt<128><<<dim3(NN / 128, NN / 128, BHN), 256>>>(
            q, k, nullptr, S, NN, NN, HD,
            (unsigned long long)NN * HD, (unsigned long long)NN * HD, (unsigned long long)NN * NN);
        // scale + mask + softmax
        softmax_k<<<BHN * NN, 128>>>(S, mask);
        // O = S @ vT.T  (batched)
        gemm_nt<64><<<dim3(HD / 64, NN / 128, BHN), 256>>>(
            S, vT, nullptr, O, NN, HD, NN,
            (unsigned long long)NN * NN, (unsigned long long)HD * NN, (unsigned long long)NN * HD);
        // reshape to [B,N,C] (reuse h as o_lin)
        o_reshape_k<<<eg(tot_o), 256>>>(O, h);
        // x += o_lin @ Wo[l].T + bo[l]
        gemm_nt<128><<<dim3(CC / 128, MM / 128, 1), 256>>>(
            h, Wo + (size_t)l * CC * CC, bo + (size_t)l * CC, t2, MM, CC, CC, 0, 0, 0);
        residual_k<<<eg(tot_xc), 256>>>(x, t2, tot_xc);
        // LN2
        layernorm_k<<<MM, 256>>>(x, ln2_g + l * CC, ln2_b + l * CC, h);
        // f = gelu(h @ W1[l].T + b1[l])  -> t [4096,4096]
        gemm_nt<128><<<dim3(FF / 128, MM / 128, 1), 256>>>(
            h, W1 + (size_t)l * FF * CC, b1 + (size_t)l * FF, t, MM, FF, CC, 0, 0, 0);
        gelu_k<<<eg(tot_ff), 256>>>(t, tot_ff);
        // x += f @ W2[l].T + b2[l]
        gemm_nt<128><<<dim3(CC / 128, MM / 128, 1), 256>>>(
            t, W2 + (size_t)l * CC * FF, b2 + (size_t)l * CC, t2, MM, CC, FF, 0, 0, 0);
        residual_k<<<eg(tot_xc), 256>>>(x, t2, tot_xc);
    }

    // out = sigmoid(x @ Wout.T + bout)
    final_k<<<MM, 64>>>(x, Wout, bout, (float*)d_out);
}

// round 2
// speedup vs baseline: 1.0000x; 1.0000x over previous
#include <cuda_runtime.h>
#include <cuda_bf16.h>
#include <math.h>

// Problem constants
#define BB 8
#define NN 512
#define CC 1024
#define HH 16
#define HD 64
#define LL 6
#define FF 4096
#define OUTD 2
#define MM (BB*NN)          // 4096 rows
#define BHN (BB*HH)         // 128 batched heads

// ---------------- scratch (static device globals; no allocation) ----------------
__device__ float g_x [MM*CC];          // residual stream
__device__ float g_h [MM*CC];          // LN output / o_lin reuse
__device__ float g_t [MM*FF];          // qkv tmp (4096x3072) / FF1 out (4096x4096)
__device__ float g_t2[MM*CC];          // proj outputs before residual add
__device__ float g_q [BHN*NN*HD];
__device__ float g_k [BHN*NN*HD];
__device__ float g_vT[BHN*HD*NN];      // V transposed: [bh][hd][n]
__device__ float g_S [BHN*NN*NN];      // attention scores (134 MB)
__device__ float g_O [BHN*NN*HD];

// ---------------- f32x2 packed helpers (sm_103a dual-rate fp32) ----------------
__device__ __forceinline__ unsigned long long pack2(float x, float y) {
    unsigned long long r;
    asm("mov.b64 %0, {%1, %2};" : "=l"(r) : "f"(x), "f"(y));
    return r;
}
__device__ __forceinline__ void fma2(unsigned long long& d, unsigned long long a, unsigned long long b) {
    asm("fma.rn.f32x2 %0, %1, %2, %0;" : "+l"(d) : "l"(a), "l"(b));
}
union U64F2 { unsigned long long u; float2 f; };

// ---------------- generic NT GEMM: C[z][m][n] = sum_k A[z][m][k]*W[z][n][k] + bias[n]
// BM=128, BN_ in {128,64}, BK=16, 256 threads, per-thread 8 x (BN_/16) tile,
// register-prefetch double buffering, f32x2 inner product.
template<int BN_>
__global__ void __launch_bounds__(256, 2)
gemm_nt(const float* __restrict__ A, const float* __restrict__ W,
        const float* __restrict__ bias, float* __restrict__ C,
        int M, int Nn, int K,
        unsigned long long sAz, unsigned long long sBz, unsigned long long sCz)
{
    constexpr int TN  = BN_ / 16;       // 8 or 4
    constexpr int LDA = 128 + 4;        // keep rows 16B aligned (132*4=528, %16==0)
    constexpr int LDB = BN_ + 4;
    constexpr int AI  = 8;              // A loads per thread per tile
    constexpr int BI  = BN_ / 16;       // W loads per thread per tile

    __shared__ float As[16][LDA];
    __shared__ float Bs[16][LDB];

    const int z = blockIdx.z;
    A += (unsigned long long)z * sAz;
    W += (unsigned long long)z * sBz;
    C += (unsigned long long)z * sCz;

    const int bm = blockIdx.y * 128;
    const int bn = blockIdx.x * BN_;
    const int tid = threadIdx.x;
    const int lk = tid & 15, lr = tid >> 4;   // loader coords
    const int tx = tid & 15, ty = tid >> 4;   // compute coords

    const float* Aptr = A + (size_t)(bm + lr) * K + lk;
    const float* Wptr = W + (size_t)(bn + lr) * K + lk;

    float pa[AI], pb[BI];
#pragma unroll
    for (int i = 0; i < AI; i++) pa[i] = Aptr[(size_t)(16 * i) * K];
#pragma unroll
    for (int i = 0; i < BI; i++) pb[i] = Wptr[(size_t)(16 * i) * K];

    unsigned long long acc[8][TN / 2] = {};

    for (int k0 = 0; k0 < K; k0 += 16) {
        // commit prefetched tile to shared
#pragma unroll
        for (int i = 0; i < AI; i++) As[lk][lr + 16 * i] = pa[i];
#pragma unroll
        for (int i = 0; i < BI; i++) Bs[lk][lr + 16 * i] = pb[i];
        __syncthreads();

        if (k0 + 16 < K) {   // issue next tile's global loads (latency overlaps compute)
            Aptr += 16; Wptr += 16;
#pragma unroll
            for (int i = 0; i < AI; i++) pa[i] = Aptr[(size_t)(16 * i) * K];
#pragma unroll
            for (int i = 0; i < BI; i++) pb[i] = Wptr[(size_t)(16 * i) * K];
        }

#pragma unroll
        for (int kk = 0; kk < 16; kk++) {
            float4 a0 = *reinterpret_cast<const float4*>(&As[kk][ty * 8]);
            float4 a1 = *reinterpret_cast<const float4*>(&As[kk][ty * 8 + 4]);
            float av[8] = {a0.x, a0.y, a0.z, a0.w, a1.x, a1.y, a1.z, a1.w};
            unsigned long long bb[TN / 2];
            const unsigned long long* bp =
                reinterpret_cast<const unsigned long long*>(&Bs[kk][tx * TN]);
#pragma unroll
            for (int jp = 0; jp < TN / 2; jp++) bb[jp] = bp[jp];
#pragma unroll
            for (int i = 0; i < 8; i++) {
                unsigned long long a2 = pack2(av[i], av[i]);
#pragma unroll
                for (int jp = 0; jp < TN / 2; jp++) fma2(acc[i][jp], a2, bb[jp]);
            }
        }
        __syncthreads();
    }

    // epilogue: + bias, vectorized float2 stores
#pragma unroll
    for (int i = 0; i < 8; i++) {
        size_t mrow = (size_t)(bm + ty * 8 + i) * Nn;
#pragma unroll
        for (int jp = 0; jp < TN / 2; jp++) {
            int n = bn + tx * TN + 2 * jp;
            U64F2 u; u.u = acc[i][jp];
            float2 r = u.f;
            if (bias) { r.x += bias[n]; r.y += bias[n + 1]; }
            *reinterpret_cast<float2*>(&C[mrow + n]) = r;
        }
    }
}

// ---------------- block reduction (broadcast result to all threads) -------------
template<bool MAXRED>
__device__ __forceinline__ float blockReduce(float val) {
    __shared__ float sh[32];
    __syncthreads();   // protect sh across repeated calls
#pragma unroll
    for (int o = 16; o > 0; o >>= 1) {
        float other = __shfl_xor_sync(0xffffffffu, val, o);
        val = MAXRED ? fmaxf(val, other) : val + other;
    }
    int w = threadIdx.x >> 5, l = threadIdx.x & 31;
    if (l == 0) sh[w] = val;
    __syncthreads();
    int nw = blockDim.x >> 5;
    if (threadIdx.x < 32) {
        val = (l < nw) ? sh[l] : (MAXRED ? -3.4e38f : 0.0f);
#pragma unroll
        for (int o = 16; o > 0; o >>= 1) {
            float other = __shfl_xor_sync(0xffffffffu, val, o);
            val = MAXRED ? fmaxf(val, other) : val + other;
        }
        if (l == 0) sh[0] = val;
    }
    __syncthreads();
    return sh[0];
}

// ---------------- layernorm: one block per row, row in registers ---------------
__global__ void layernorm_k(const float* __restrict__ x, const float* __restrict__ g,
                            const float* __restrict__ b, float* __restrict__ h)
{
    int row = blockIdx.x;
    int tid = threadIdx.x;                    // 256 threads, 4 elems each
    const float* xr = x + (size_t)row * CC;
    float v[4];
#pragma unroll
    for (int i = 0; i < 4; i++) v[i] = xr[tid + 256 * i];
    float s = v[0] + v[1] + v[2] + v[3];
    s = blockReduce<false>(s);
    float mu = s * (1.0f / CC);
    float d0 = v[0] - mu, d1 = v[1] - mu, d2 = v[2] - mu, d3 = v[3] - mu;
    float s2 = d0 * d0 + d1 * d1 + d2 * d2 + d3 * d3;
    s2 = blockReduce<false>(s2);
    float inv = rsqrtf(s2 * (1.0f / CC) + 1e-6f);
    float* hr = h + (size_t)row * CC;
#pragma unroll
    for (int i = 0; i < 4; i++) {
        int c = tid + 256 * i;
        hr[c] = (v[i] - mu) * inv * g[c] + b[c];
    }
}

// ---------------- masked softmax over S rows (row len 512) ---------------------
__global__ void softmax_k(float* __restrict__ S, const int* __restrict__ mask)
{
    int r = blockIdx.x;                    // 0..BH*N-1
    int b = r >> 13;                       // r / (H*N) = r / 8192
    float* row = S + (size_t)r * NN;
    const int* mrow = mask + b * NN;
    int tid = threadIdx.x;                 // 128 threads, 4 elems each
    float v[4];
#pragma unroll
    for (int i = 0; i < 4; i++) {
        int k = tid + 128 * i;
        float t = row[k] * 0.125f;         // scale = HD^-0.5 = 1/8
        if (mrow[k] == 0) t = -1e9f;
        v[i] = t;
    }
    float m = fmaxf(fmaxf(v[0], v[1]), fmaxf(v[2], v[3]));
    m = blockReduce<true>(m);
    float e[4], s = 0.0f;
#pragma unroll
    for (int i = 0; i < 4; i++) { e[i] = expf(v[i] - m); s += e[i]; }
    s = blockReduce<false>(s);
    float inv = 1.0f / s;
#pragma unroll
    for (int i = 0; i < 4; i++) row[tid + 128 * i] = e[i] * inv;
}

// ---------------- small elementwise kernels ------------------------------------
__global__ void add_pos_k(float* __restrict__ x, const float* __restrict__ pos, int total) {
    int i = blockIdx.x * blockDim.x + threadIdx.x;
    if (i < total) x[i] += pos[i % (NN * CC)];
}
__global__ void residual_k(float* __restrict__ x, const float* __restrict__ t, int total) {
    int i = blockIdx.x * blockDim.x + threadIdx.x;
    if (i < total) x[i] += t[i];
}
__global__ void gelu_k(float* __restrict__ t, int total) {
    int i = blockIdx.x * blockDim.x + threadIdx.x;
    if (i < total) {
        float v = t[i];
        t[i] = 0.5f * v * (1.0f + erff(v * 0.70710678118654752f));
    }
}
__global__ void qkv_scatter_k(const float* __restrict__ t, float* __restrict__ q,
                              float* __restrict__ k, float* __restrict__ vT) {
    int i = blockIdx.x * blockDim.x + threadIdx.x;
    if (i >= MM * 3 * CC) return;
    int m = i / (3 * CC), c = i - m * (3 * CC);
    int which = c >> 10;          // 0=q 1=k 2=v
    int ci = c & 1023;
    int head = ci >> 6, hd = ci & 63;
    int b = m >> 9, n = m & 511;
    int bh = b * HH + head;
    float v = t[i];
    if (which == 0)      q[((size_t)bh * NN + n) * HD + hd] = v;
    else if (which == 1) k[((size_t)bh * NN + n) * HD + hd] = v;
    else                 vT[((size_t)bh * HD + hd) * NN + n] = v;
}
__global__ void o_reshape_k(const float* __restrict__ O, float* __restrict__ o_lin) {
    int i = blockIdx.x * blockDim.x + threadIdx.x;
    if (i >= BHN * NN * HD) return;
    int bh = i / (NN * HD);
    int rem = i - bh * (NN * HD);
    int n = rem >> 6, hd = rem & 63;
    int b = bh >> 4, head = bh & 15;
    o_lin[((size_t)(b * NN + n)) * CC + head * HD + hd] = O[i];
}
// final: out[m][j] = sigmoid(x[m] . Wout[j] + bout[j]); one warp per (m,j)
__global__ void final_k(const float* __restrict__ x, const float* __restrict__ Wout,
                        const float* __restrict__ bout, float* __restrict__ out) {
    int m = blockIdx.x;
    int j = threadIdx.x >> 5;
    int lane = threadIdx.x & 31;
    const float* xr = x + (size_t)m * CC;
    const float* w  = Wout + (size_t)j * CC;
    float s = 0.0f;
#pragma unroll
    for (int t = 0; t < CC / 32; t++) s += xr[lane + 32 * t] * w[lane + 32 * t];
#pragma unroll
    for (int o = 16; o > 0; o >>= 1) s += __shfl_xor_sync(0xffffffffu, s, o);
    if (lane == 0) out[m * OUTD + j] = 1.0f / (1.0f + expf(-(s + bout[j])));
}

// ---------------- driver ---------------------------------------------------------
static inline dim3 eg(int total) { return dim3((total + 255) / 256); }

extern "C" void kernel_launch(void* const* d_in, const int* in_sizes, int n_in,
                              void* d_out, int out_size)
{
    (void)in_sizes; (void)n_in; (void)out_size;
    const float* inputs = (const float*)d_in[0];
    const int*   mask   = (const int*)  d_in[1];
    const float* pos    = (const float*)d_in[2];
    const float* Wi     = (const float*)d_in[3];
    const float* bi     = (const float*)d_in[4];
    const float* ln1_g  = (const float*)d_in[5];
    const float* ln1_b  = (const float*)d_in[6];
    const float* Wqkv   = (const float*)d_in[7];
    const float* bqkv   = (const float*)d_in[8];
    const float* Wo     = (const float*)d_in[9];
    const float* bo     = (const float*)d_in[10];
    const float* ln2_g  = (const float*)d_in[11];
    const float* ln2_b  = (const float*)d_in[12];
    const float* W1     = (const float*)d_in[13];
    const float* b1     = (const float*)d_in[14];
    const float* W2     = (const float*)d_in[15];
    const float* b2     = (const float*)d_in[16];
    const float* Wout   = (const float*)d_in[17];
    const float* bout   = (const float*)d_in[18];

    float *x, *h, *t, *t2, *q, *k, *vT, *S, *O;
    cudaGetSymbolAddress((void**)&x,  g_x);
    cudaGetSymbolAddress((void**)&h,  g_h);
    cudaGetSymbolAddress((void**)&t,  g_t);
    cudaGetSymbolAddress((void**)&t2, g_t2);
    cudaGetSymbolAddress((void**)&q,  g_q);
    cudaGetSymbolAddress((void**)&k,  g_k);
    cudaGetSymbolAddress((void**)&vT, g_vT);
    cudaGetSymbolAddress((void**)&S,  g_S);
    cudaGetSymbolAddress((void**)&O,  g_O);

    const int tot_xc = MM * CC;        // 4.19M
    const int tot_qkv = MM * 3 * CC;   // 12.6M
    const int tot_ff = MM * FF;        // 16.8M
    const int tot_o = BHN * NN * HD;   // 4.19M

    // x = inputs @ Wi.T + bi ; x += pos
    gemm_nt<128><<<dim3(CC / 128, MM / 128, 1), 256>>>(inputs, Wi, bi, x, MM, CC, CC, 0, 0, 0);
    add_pos_k<<<eg(tot_xc), 256>>>(x, pos, tot_xc);

    for (int l = 0; l < LL; l++) {
        // LN1
        layernorm_k<<<MM, 256>>>(x, ln1_g + l * CC, ln1_b + l * CC, h);
        // qkv = h @ Wqkv[l].T + bqkv[l]  -> t [4096,3072]
        gemm_nt<128><<<dim3(3 * CC / 128, MM / 128, 1), 256>>>(
            h, Wqkv + (size_t)l * 3 * CC * CC, bqkv + (size_t)l * 3 * CC, t, MM, 3 * CC, CC, 0, 0, 0);
        qkv_scatter_k<<<eg(tot_qkv), 256>>>(t, q, k, vT);
        // S = q @ k.T  (batched over 128 heads)
        gemm_nt<128><<<dim3(NN / 128, NN / 128, BHN), 256>>>(
            q, k, nullptr, S, NN, NN, HD,
            (unsigned long long)NN * HD, (unsigned long long)NN * HD, (unsigned long long)NN * NN);
        // scale + mask + softmax
        softmax_k<<<BHN * NN, 128>>>(S, mask);
        // O = S @ vT.T  (batched)
        gemm_nt<64><<<dim3(HD / 64, NN / 128, BHN), 256>>>(
            S, vT, nullptr, O, NN, HD, NN,
            (unsigned long long)NN * NN, (unsigned long long)HD * NN, (unsigned long long)NN * HD);
        // reshape to [B,N,C] (reuse h as o_lin)
        o_reshape_k<<<eg(tot_o), 256>>>(O, h);
        // x += o_lin @ Wo[l].T + bo[l]
        gemm_nt<128><<<dim3(CC / 128, MM / 128, 1), 256>>>(
            h, Wo + (size_t)l * CC * CC, bo + (size_t)l * CC, t2, MM, CC, CC, 0, 0, 0);
        residual_k<<<eg(tot_xc), 256>>>(x, t2, tot_xc);
        // LN2
        layernorm_k<<<MM, 256>>>(x, ln2_g + l * CC, ln2_b + l * CC, h);
        // f = gelu(h @ W1[l].T + b1[l])  -> t [4096,4096]
        gemm_nt<128><<<dim3(FF / 128, MM / 128, 1), 256>>>(
            h, W1 + (size_t)l * FF * CC, b1 + (size_t)l * FF, t, MM, FF, CC, 0, 0, 0);
        gelu_k<<<eg(tot_ff), 256>>>(t, tot_ff);
        // x += f @ W2[l].T + b2[l]
        gemm_nt<128><<<dim3(CC / 128, MM / 128, 1), 256>>>(
            t, W2 + (size_t)l * CC * FF, b2 + (size_t)l * CC, t2, MM, CC, FF, 0, 0, 0);
        residual_k<<<eg(tot_xc), 256>>>(x, t2, tot_xc);
    }

    // out = sigmoid(x @ Wout.T + bout)
    final_k<<<MM, 64>>>(x, Wout, bout, (float*)d_out);
}

// round 5
// speedup vs baseline: 1.8131x; 1.8130x over previous
#include <cuda_runtime.h>
#include <cuda_bf16.h>
#include <math.h>
#include <stdint.h>

#define BB 8
#define NN 512
#define CC 1024
#define HH 16
#define HD 64
#define LL 6
#define FF 4096
#define OUTD 2
#define MM (BB*NN)
#define BHN (BB*HH)

// mma.sync GEMM tiling: 128x128x32, 8 warps (2 m x 4 n), warp tile 64x32
#define TILE_SB 10240              // 128 rows * 80 B
#define STAGE_SB (4*TILE_SB)       // Ah,Al,Bh,Bl
#define DYN_SB (2*STAGE_SB)        // 81920

// weight hi/lo offsets (elements)
#define OFF_WI   0ULL
#define OFF_WQKV 1048576ULL
#define OFF_WO   19922944ULL
#define OFF_W1   26214400ULL
#define OFF_W2   51380224ULL
#define WELEMS   76546048ULL

// ---- scratch ----
__device__ float g_x [MM*CC];
__device__ float g_t [MM*FF];
__device__ float g_t2[MM*CC];
__device__ float g_q [BHN*NN*HD];
__device__ float g_k [BHN*NN*HD];
__device__ float g_vT[BHN*HD*NN];
__device__ float g_S [BHN*NN*NN];
__device__ float g_O [BHN*NN*HD];
__device__ __nv_bfloat16 g_ah[MM*FF];
__device__ __nv_bfloat16 g_al[MM*FF];
__device__ __nv_bfloat16 g_wh[WELEMS];
__device__ __nv_bfloat16 g_wl[WELEMS];

__device__ __forceinline__ uint32_t smem_u32(const void* p) {
    uint32_t a;
    asm("{ .reg .u64 t; cvta.to.shared.u64 t, %1; cvt.u32.u64 %0, t; }" : "=r"(a) : "l"(p));
    return a;
}
__device__ __forceinline__ void ldsm4(uint32_t& r0, uint32_t& r1, uint32_t& r2, uint32_t& r3, uint32_t a) {
    asm volatile("ldmatrix.sync.aligned.m8n8.x4.shared.b16 {%0,%1,%2,%3},[%4];"
                 : "=r"(r0), "=r"(r1), "=r"(r2), "=r"(r3) : "r"(a));
}
__device__ __forceinline__ void ldsm2(uint32_t& r0, uint32_t& r1, uint32_t a) {
    asm volatile("ldmatrix.sync.aligned.m8n8.x2.shared.b16 {%0,%1},[%2];"
                 : "=r"(r0), "=r"(r1) : "r"(a));
}
__device__ __forceinline__ void mma16816(float* c, const uint32_t* a, const uint32_t* b) {
    asm volatile(
        "mma.sync.aligned.m16n8k16.row.col.f32.bf16.bf16.f32 "
        "{%0,%1,%2,%3},{%4,%5,%6,%7},{%8,%9},{%0,%1,%2,%3};"
        : "+f"(c[0]), "+f"(c[1]), "+f"(c[2]), "+f"(c[3])
        : "r"(a[0]), "r"(a[1]), "r"(a[2]), "r"(a[3]), "r"(b[0]), "r"(b[1]));
}

// ---- bf16x3 NT GEMM via mma.sync: C = (Ah+Al)(Bh+Bl)^T + bias (drops Al*Bl) ----
__global__ void __launch_bounds__(256)
gemm_bf3(const __nv_bfloat16* __restrict__ Ah, const __nv_bfloat16* __restrict__ Al,
         const __nv_bfloat16* __restrict__ Bh, const __nv_bfloat16* __restrict__ Bl,
         const float* __restrict__ bias, float* __restrict__ C, int Nn, int K)
{
    extern __shared__ unsigned char sm[];
    const uint32_t sbase = smem_u32(sm);
    const int tid = threadIdx.x, lane = tid & 31, wid = tid >> 5;
    const int wm = wid & 1, wn = wid >> 1;
    const int bm = blockIdx.y * 128, bn = blockIdx.x * 128;
    const int nc = K >> 5;

    auto load_stage = [&](int buf, int chunk) {
        const int k0 = chunk * 32;
        const int r0 = tid >> 2, cc = tid & 3;
#pragma unroll
        for (int i = 0; i < 8; i++) {
            const int tile = i >> 1;
            const int r = r0 + 64 * (i & 1);
            const __nv_bfloat16* g;
            if (tile == 0)      g = Ah + (size_t)(bm + r) * K;
            else if (tile == 1) g = Al + (size_t)(bm + r) * K;
            else if (tile == 2) g = Bh + (size_t)(bn + r) * K;
            else                g = Bl + (size_t)(bn + r) * K;
            g += k0 + cc * 8;
            uint32_t s = sbase + buf * STAGE_SB + tile * TILE_SB + r * 80 + cc * 16;
            asm volatile("cp.async.cg.shared.global [%0], [%1], 16;" :: "r"(s), "l"(g));
        }
        asm volatile("cp.async.commit_group;");
    };

    float acc[4][4][4] = {};

    load_stage(0, 0);
    load_stage(1, 1);
    asm volatile("cp.async.wait_group 1;");
    __syncthreads();

    for (int c = 0; c < nc; c++) {
        const uint32_t sb = sbase + (c & 1) * STAGE_SB;
#pragma unroll
        for (int k16 = 0; k16 < 2; k16++) {
            uint32_t ah[4][4], al[4][4], bh[4][2], bl[4][2];
            const uint32_t acol = k16 * 32 + (lane >> 4) * 16;
            const uint32_t bcol = k16 * 32 + ((lane >> 3) & 1) * 16;
#pragma unroll
            for (int mt = 0; mt < 4; mt++) {
                uint32_t ad = sb + (wm * 64 + mt * 16 + (lane & 15)) * 80 + acol;
                ldsm4(ah[mt][0], ah[mt][1], ah[mt][2], ah[mt][3], ad);
                ldsm4(al[mt][0], al[mt][1], al[mt][2], al[mt][3], ad + TILE_SB);
            }
#pragma unroll
            for (int nt = 0; nt < 4; nt++) {
                uint32_t bd = sb + 2 * TILE_SB + (wn * 32 + nt * 8 + (lane & 7)) * 80 + bcol;
                ldsm2(bh[nt][0], bh[nt][1], bd);
                ldsm2(bl[nt][0], bl[nt][1], bd + TILE_SB);
            }
#pragma unroll
            for (int mt = 0; mt < 4; mt++)
#pragma unroll
                for (int nt = 0; nt < 4; nt++) {
                    mma16816(acc[mt][nt], ah[mt], bh[nt]);
                    mma16816(acc[mt][nt], ah[mt], bl[nt]);
                    mma16816(acc[mt][nt], al[mt], bh[nt]);
                }
        }
        __syncthreads();
        if (c + 2 < nc) load_stage(c & 1, c + 2);
        asm volatile("cp.async.wait_group 1;");
        __syncthreads();
    }

#pragma unroll
    for (int mt = 0; mt < 4; mt++)
#pragma unroll
        for (int nt = 0; nt < 4; nt++) {
            int row = bm + wm * 64 + mt * 16 + (lane >> 2);
            int col = bn + wn * 32 + nt * 8 + (lane & 3) * 2;
            float b0 = bias ? bias[col] : 0.0f;
            float b1 = bias ? bias[col + 1] : 0.0f;
            float2 v0 = { acc[mt][nt][0] + b0, acc[mt][nt][1] + b1 };
            float2 v1 = { acc[mt][nt][2] + b0, acc[mt][nt][3] + b1 };
            *reinterpret_cast<float2*>(&C[(size_t)row * Nn + col]) = v0;
            *reinterpret_cast<float2*>(&C[(size_t)(row + 8) * Nn + col]) = v1;
        }
}

// ---- f32x2 NT GEMM (attention) ----
__device__ __forceinline__ unsigned long long pack2(float x, float y) {
    unsigned long long r;
    asm("mov.b64 %0, {%1, %2};" : "=l"(r) : "f"(x), "f"(y));
    return r;
}
__device__ __forceinline__ void fma2(unsigned long long& d, unsigned long long a, unsigned long long b) {
    asm("fma.rn.f32x2 %0, %1, %2, %0;" : "+l"(d) : "l"(a), "l"(b));
}
union U64F2 { unsigned long long u; float2 f; };

template<int BN_>
__global__ void __launch_bounds__(256, 2)
gemm_nt(const float* __restrict__ A, const float* __restrict__ W,
        float* __restrict__ C, int M, int Nn, int K,
        unsigned long long sAz, unsigned long long sBz, unsigned long long sCz)
{
    constexpr int TN = BN_ / 16, LDA = 132, LDB = BN_ + 4, AI = 8, BI = BN_ / 16;
    __shared__ float As[16][LDA];
    __shared__ float Bs[16][LDB];
    const int z = blockIdx.z;
    A += (unsigned long long)z * sAz; W += (unsigned long long)z * sBz; C += (unsigned long long)z * sCz;
    const int bm = blockIdx.y * 128, bn = blockIdx.x * BN_;
    const int tid = threadIdx.x;
    const int lk = tid & 15, lr = tid >> 4, tx = tid & 15, ty = tid >> 4;
    const float* Aptr = A + (size_t)(bm + lr) * K + lk;
    const float* Wptr = W + (size_t)(bn + lr) * K + lk;
    float pa[AI], pb[BI];
#pragma unroll
    for (int i = 0; i < AI; i++) pa[i] = Aptr[(size_t)(16 * i) * K];
#pragma unroll
    for (int i = 0; i < BI; i++) pb[i] = Wptr[(size_t)(16 * i) * K];
    unsigned long long acc[8][TN / 2] = {};
    for (int k0 = 0; k0 < K; k0 += 16) {
#pragma unroll
        for (int i = 0; i < AI; i++) As[lk][lr + 16 * i] = pa[i];
#pragma unroll
        for (int i = 0; i < BI; i++) Bs[lk][lr + 16 * i] = pb[i];
        __syncthreads();
        if (k0 + 16 < K) {
            Aptr += 16; Wptr += 16;
#pragma unroll
            for (int i = 0; i < AI; i++) pa[i] = Aptr[(size_t)(16 * i) * K];
#pragma unroll
            for (int i = 0; i < BI; i++) pb[i] = Wptr[(size_t)(16 * i) * K];
        }
#pragma unroll
        for (int kk = 0; kk < 16; kk++) {
            float4 a0 = *reinterpret_cast<const float4*>(&As[kk][ty * 8]);
            float4 a1 = *reinterpret_cast<const float4*>(&As[kk][ty * 8 + 4]);
            float av[8] = {a0.x, a0.y, a0.z, a0.w, a1.x, a1.y, a1.z, a1.w};
            unsigned long long bb[TN / 2];
            const unsigned long long* bp = reinterpret_cast<const unsigned long long*>(&Bs[kk][tx * TN]);
#pragma unroll
            for (int jp = 0; jp < TN / 2; jp++) bb[jp] = bp[jp];
#pragma unroll
            for (int i = 0; i < 8; i++) {
                unsigned long long a2 = pack2(av[i], av[i]);
#pragma unroll
                for (int jp = 0; jp < TN / 2; jp++) fma2(acc[i][jp], a2, bb[jp]);
            }
        }
        __syncthreads();
    }
#pragma unroll
    for (int i = 0; i < 8; i++) {
        size_t mrow = (size_t)(bm + ty * 8 + i) * Nn;
#pragma unroll
        for (int jp = 0; jp < TN / 2; jp++) {
            U64F2 u; u.u = acc[i][jp];
            *reinterpret_cast<float2*>(&C[mrow + bn + tx * TN + 2 * jp]) = u.f;
        }
    }
}

// ---- reductions / elementwise ----
template<bool MAXRED>
__device__ __forceinline__ float blockReduce(float val) {
    __shared__ float sh[32];
    __syncthreads();
#pragma unroll
    for (int o = 16; o > 0; o >>= 1) {
        float t = __shfl_xor_sync(0xffffffffu, val, o);
        val = MAXRED ? fmaxf(val, t) : val + t;
    }
    int w = threadIdx.x >> 5, l = threadIdx.x & 31;
    if (l == 0) sh[w] = val;
    __syncthreads();
    int nw = blockDim.x >> 5;
    if (threadIdx.x < 32) {
        val = (l < nw) ? sh[l] : (MAXRED ? -3.4e38f : 0.0f);
#pragma unroll
        for (int o = 16; o > 0; o >>= 1) {
            float t = __shfl_xor_sync(0xffffffffu, val, o);
            val = MAXRED ? fmaxf(val, t) : val + t;
        }
        if (l == 0) sh[0] = val;
    }
    __syncthreads();
    return sh[0];
}
__device__ __forceinline__ void split1(float v, __nv_bfloat16& h, __nv_bfloat16& l) {
    h = __float2bfloat16_rn(v);
    l = __float2bfloat16_rn(v - __bfloat162float(h));
}

__global__ void layernorm_split_k(const float* __restrict__ x, const float* __restrict__ g,
                                  const float* __restrict__ b,
                                  __nv_bfloat16* __restrict__ oh, __nv_bfloat16* __restrict__ ol)
{
    int row = blockIdx.x, tid = threadIdx.x;
    const float* xr = x + (size_t)row * CC;
    float v[4];
#pragma unroll
    for (int i = 0; i < 4; i++) v[i] = xr[tid + 256 * i];
    float s = blockReduce<false>(v[0] + v[1] + v[2] + v[3]);
    float mu = s * (1.0f / CC);
    float d0 = v[0]-mu, d1 = v[1]-mu, d2 = v[2]-mu, d3 = v[3]-mu;
    float s2 = blockReduce<false>(d0*d0 + d1*d1 + d2*d2 + d3*d3);
    float inv = rsqrtf(s2 * (1.0f / CC) + 1e-6f);
#pragma unroll
    for (int i = 0; i < 4; i++) {
        int c = tid + 256 * i;
        float r = (v[i] - mu) * inv * g[c] + b[c];
        __nv_bfloat16 hh, lo; split1(r, hh, lo);
        oh[(size_t)row * CC + c] = hh;
        ol[(size_t)row * CC + c] = lo;
    }
}

__global__ void softmax_k(float* __restrict__ S, const int* __restrict__ mask)
{
    int r = blockIdx.x, b = r >> 13;
    float* row = S + (size_t)r * NN;
    const int* mrow = mask + b * NN;
    int tid = threadIdx.x;
    float v[4];
#pragma unroll
    for (int i = 0; i < 4; i++) {
        int k = tid + 128 * i;
        float t = row[k] * 0.125f;
        if (mrow[k] == 0) t = -1e9f;
        v[i] = t;
    }
    float m = blockReduce<true>(fmaxf(fmaxf(v[0], v[1]), fmaxf(v[2], v[3])));
    float e[4], s = 0.0f;
#pragma unroll
    for (int i = 0; i < 4; i++) { e[i] = expf(v[i] - m); s += e[i]; }
    s = blockReduce<false>(s);
    float inv = 1.0f / s;
#pragma unroll
    for (int i = 0; i < 4; i++) row[tid + 128 * i] = e[i] * inv;
}

__global__ void split_k(const float* __restrict__ s, __nv_bfloat16* __restrict__ h,
                        __nv_bfloat16* __restrict__ l, int n) {
    int i = blockIdx.x * blockDim.x + threadIdx.x;
    if (i < n) { __nv_bfloat16 hh, lo; split1(s[i], hh, lo); h[i] = hh; l[i] = lo; }
}
__global__ void add_pos_k(float* __restrict__ x, const float* __restrict__ pos, int total) {
    int i = blockIdx.x * blockDim.x + threadIdx.x;
    if (i < total) x[i] += pos[i % (NN * CC)];
}
__global__ void residual_k(float* __restrict__ x, const float* __restrict__ t, int total) {
    int i = blockIdx.x * blockDim.x + threadIdx.x;
    if (i < total) x[i] += t[i];
}
__global__ void gelu_split_k(const float* __restrict__ t, __nv_bfloat16* __restrict__ oh,
                             __nv_bfloat16* __restrict__ ol, int total) {
    int i = blockIdx.x * blockDim.x + threadIdx.x;
    if (i < total) {
        float v = t[i];
        float r = 0.5f * v * (1.0f + erff(v * 0.70710678118654752f));
        __nv_bfloat16 hh, lo; split1(r, hh, lo);
        oh[i] = hh; ol[i] = lo;
    }
}
__global__ void qkv_scatter_k(const float* __restrict__ t, float* __restrict__ q,
                              float* __restrict__ k, float* __restrict__ vT) {
    int i = blockIdx.x * blockDim.x + threadIdx.x;
    if (i >= MM * 3 * CC) return;
    int m = i / (3 * CC), c = i - m * (3 * CC);
    int which = c >> 10, ci = c & 1023;
    int head = ci >> 6, hd = ci & 63;
    int b = m >> 9, n = m & 511;
    int bh = b * HH + head;
    float v = t[i];
    if (which == 0)      q[((size_t)bh * NN + n) * HD + hd] = v;
    else if (which == 1) k[((size_t)bh * NN + n) * HD + hd] = v;
    else                 vT[((size_t)bh * HD + hd) * NN + n] = v;
}
__global__ void o_reshape_split_k(const float* __restrict__ O, __nv_bfloat16* __restrict__ oh,
                                  __nv_bfloat16* __restrict__ ol) {
    int i = blockIdx.x * blockDim.x + threadIdx.x;
    if (i >= BHN * NN * HD) return;
    int bh = i / (NN * HD), rem = i - bh * (NN * HD);
    int n = rem >> 6, hd = rem & 63;
    int b = bh >> 4, head = bh & 15;
    size_t o = ((size_t)(b * NN + n)) * CC + head * HD + hd;
    __nv_bfloat16 hh, lo; split1(O[i], hh, lo);
    oh[o] = hh; ol[o] = lo;
}
__global__ void final_k(const float* __restrict__ x, const float* __restrict__ Wout,
                        const float* __restrict__ bout, float* __restrict__ out) {
    int m = blockIdx.x, j = threadIdx.x >> 5, lane = threadIdx.x & 31;
    const float* xr = x + (size_t)m * CC;
    const float* w  = Wout + (size_t)j * CC;
    float s = 0.0f;
#pragma unroll
    for (int t = 0; t < CC / 32; t++) s += xr[lane + 32 * t] * w[lane + 32 * t];
#pragma unroll
    for (int o = 16; o > 0; o >>= 1) s += __shfl_xor_sync(0xffffffffu, s, o);
    if (lane == 0) out[m * OUTD + j] = 1.0f / (1.0f + expf(-(s + bout[j])));
}

// ---- host ----
static void launch_bf3(const __nv_bfloat16* ah, const __nv_bfloat16* al,
                       const __nv_bfloat16* wh, const __nv_bfloat16* wl,
                       const float* bias, float* C, int Nn, int K) {
    gemm_bf3<<<dim3(Nn / 128, MM / 128), 256, DYN_SB>>>(ah, al, wh, wl, bias, C, Nn, K);
}
static inline dim3 eg(int total) { return dim3((total + 255) / 256); }

extern "C" void kernel_launch(void* const* d_in, const int* in_sizes, int n_in,
                              void* d_out, int out_size)
{
    (void)in_sizes; (void)n_in; (void)out_size;
    const float* inputs = (const float*)d_in[0];
    const int*   mask   = (const int*)  d_in[1];
    const float* pos    = (const float*)d_in[2];
    const float* Wi     = (const float*)d_in[3];
    const float* bi     = (const float*)d_in[4];
    const float* ln1_g  = (const float*)d_in[5];
    const float* ln1_b  = (const float*)d_in[6];
    const float* Wqkv   = (const float*)d_in[7];
    const float* bqkv   = (const float*)d_in[8];
    const float* Wo     = (const float*)d_in[9];
    const float* bo     = (const float*)d_in[10];
    const float* ln2_g  = (const float*)d_in[11];
    const float* ln2_b  = (const float*)d_in[12];
    const float* W1     = (const float*)d_in[13];
    const float* b1     = (const float*)d_in[14];
    const float* W2     = (const float*)d_in[15];
    const float* b2     = (const float*)d_in[16];
    const float* Wout   = (const float*)d_in[17];
    const float* bout   = (const float*)d_in[18];

    float *x, *t, *t2, *q, *k, *vT, *S, *O;
    __nv_bfloat16 *ah, *al, *wh, *wl;
    cudaGetSymbolAddress((void**)&x,  g_x);
    cudaGetSymbolAddress((void**)&t,  g_t);
    cudaGetSymbolAddress((void**)&t2, g_t2);
    cudaGetSymbolAddress((void**)&q,  g_q);
    cudaGetSymbolAddress((void**)&k,  g_k);
    cudaGetSymbolAddress((void**)&vT, g_vT);
    cudaGetSymbolAddress((void**)&S,  g_S);
    cudaGetSymbolAddress((void**)&O,  g_O);
    cudaGetSymbolAddress((void**)&ah, g_ah);
    cudaGetSymbolAddress((void**)&al, g_al);
    cudaGetSymbolAddress((void**)&wh, g_wh);
    cudaGetSymbolAddress((void**)&wl, g_wl);

    cudaFuncSetAttribute(gemm_bf3, cudaFuncAttributeMaxDynamicSharedMemorySize, DYN_SB);

    const int tot_xc = MM * CC, tot_qkv = MM * 3 * CC, tot_ff = MM * FF, tot_o = BHN * NN * HD;

    // split all weights to bf16 hi/lo
    split_k<<<eg(CC * CC), 256>>>(Wi,   wh + OFF_WI,   wl + OFF_WI,   CC * CC);
    split_k<<<eg(LL*3*CC*CC), 256>>>(Wqkv, wh + OFF_WQKV, wl + OFF_WQKV, LL*3*CC*CC);
    split_k<<<eg(LL*CC*CC), 256>>>(Wo,  wh + OFF_WO,   wl + OFF_WO,   LL*CC*CC);
    split_k<<<eg(LL*FF*CC), 256>>>(W1,  wh + OFF_W1,   wl + OFF_W1,   LL*FF*CC);
    split_k<<<eg(LL*CC*FF), 256>>>(W2,  wh + OFF_W2,   wl + OFF_W2,   LL*CC*FF);

    // x = inputs @ Wi.T + bi ; x += pos
    split_k<<<eg(tot_xc), 256>>>(inputs, ah, al, tot_xc);
    launch_bf3(ah, al, wh + OFF_WI, wl + OFF_WI, bi, x, CC, CC);
    add_pos_k<<<eg(tot_xc), 256>>>(x, pos, tot_xc);

    for (int l = 0; l < LL; l++) {
        const size_t oq = OFF_WQKV + (size_t)l * 3 * CC * CC;
        const size_t oo = OFF_WO   + (size_t)l * CC * CC;
        const size_t o1 = OFF_W1   + (size_t)l * FF * CC;
        const size_t o2 = OFF_W2   + (size_t)l * CC * FF;

        layernorm_split_k<<<MM, 256>>>(x, ln1_g + l * CC, ln1_b + l * CC, ah, al);
        launch_bf3(ah, al, wh + oq, wl + oq, bqkv + (size_t)l * 3 * CC, t, 3 * CC, CC);
        qkv_scatter_k<<<eg(tot_qkv), 256>>>(t, q, k, vT);

        gemm_nt<128><<<dim3(NN/128, NN/128, BHN), 256>>>(q, k, S, NN, NN, HD,
            (unsigned long long)NN*HD, (unsigned long long)NN*HD, (unsigned long long)NN*NN);
        softmax_k<<<BHN * NN, 128>>>(S, mask);
        gemm_nt<64><<<dim3(HD/64, NN/128, BHN), 256>>>(S, vT, O, NN, HD, NN,
            (unsigned long long)NN*NN, (unsigned long long)HD*NN, (unsigned long long)NN*HD);

        o_reshape_split_k<<<eg(tot_o), 256>>>(O, ah, al);
        launch_bf3(ah, al, wh + oo, wl + oo, bo + (size_t)l * CC, t2, CC, CC);
        residual_k<<<eg(tot_xc), 256>>>(x, t2, tot_xc);

        layernorm_split_k<<<MM, 256>>>(x, ln2_g + l * CC, ln2_b + l * CC, ah, al);
        launch_bf3(ah, al, wh + o1, wl + o1, b1 + (size_t)l * FF, t, FF, CC);
        gelu_split_k<<<eg(tot_ff), 256>>>(t, ah, al, tot_ff);
        launch_bf3(ah, al, wh + o2, wl + o2, b2 + (size_t)l * CC, t2, CC, FF);
        residual_k<<<eg(tot_xc), 256>>>(x, t2, tot_xc);
    }

    final_k<<<MM, 64>>>(x, Wout, bout, (float*)d_out);
}

// round 9
// speedup vs baseline: 1.9768x; 1.0903x over previous
#include <cuda_runtime.h>
#include <cuda_bf16.h>
#include <math.h>
#include <stdint.h>

#define BB 8
#define NN 512
#define CC 1024
#define HH 16
#define HD 64
#define LL 6
#define FF 4096
#define OUTD 2
#define MM (BB*NN)
#define BHN (BB*HH)

// gemm_bf3 tiling: 128x256x32, 512 threads (4m x 4n warps, warp tile 32x64)
#define ROWB 80
#define OFF_AL 10240
#define OFF_BH 20480
#define OFF_BL 40960
#define STAGE_SB 61440
#define DYN_SB (2*STAGE_SB)   // 122880

// weight hi/lo offsets (elements)
#define OFF_WI   0ULL
#define OFF_WQKV 1048576ULL
#define OFF_WO   19922944ULL
#define OFF_W1   26214400ULL
#define OFF_W2   51380224ULL
#define WELEMS   76546048ULL

// ---- scratch ----
__device__ float g_x [MM*CC];
__device__ float g_q [BHN*NN*HD];
__device__ float g_k [BHN*NN*HD];
__device__ float g_vT[BHN*HD*NN];
__device__ float g_S [BHN*NN*NN];
__device__ __nv_bfloat16 g_ah[MM*CC];
__device__ __nv_bfloat16 g_al[MM*CC];
__device__ __nv_bfloat16 g_fh[MM*FF];
__device__ __nv_bfloat16 g_fl[MM*FF];
__device__ __nv_bfloat16 g_wh[WELEMS];
__device__ __nv_bfloat16 g_wl[WELEMS];

__device__ __forceinline__ uint32_t smem_u32(const void* p) {
    uint32_t a;
    asm("{ .reg .u64 t; cvta.to.shared.u64 t, %1; cvt.u32.u64 %0, t; }" : "=r"(a) : "l"(p));
    return a;
}
__device__ __forceinline__ void ldsm4(uint32_t& r0, uint32_t& r1, uint32_t& r2, uint32_t& r3, uint32_t a) {
    asm volatile("ldmatrix.sync.aligned.m8n8.x4.shared.b16 {%0,%1,%2,%3},[%4];"
                 : "=r"(r0), "=r"(r1), "=r"(r2), "=r"(r3) : "r"(a));
}
__device__ __forceinline__ void mma16816(float* c, const uint32_t* a, const uint32_t* b) {
    asm volatile(
        "mma.sync.aligned.m16n8k16.row.col.f32.bf16.bf16.f32 "
        "{%0,%1,%2,%3},{%4,%5,%6,%7},{%8,%9},{%0,%1,%2,%3};"
        : "+f"(c[0]), "+f"(c[1]), "+f"(c[2]), "+f"(c[3])
        : "r"(a[0]), "r"(a[1]), "r"(a[2]), "r"(a[3]), "r"(b[0]), "r"(b[1]));
}
__device__ __forceinline__ void split1(float v, __nv_bfloat16& h, __nv_bfloat16& l) {
    h = __float2bfloat16_rn(v);
    l = __float2bfloat16_rn(v - __bfloat162float(h));
}
__device__ __forceinline__ float gelu1(float v) {
    return 0.5f * v * (1.0f + erff(v * 0.70710678118654752f));
}

// MODE: 1=OUT_POS(x=acc+bias+pos) 2=QKV(scatter q*0.125,k,vT) 3=RESID(C+=acc+bias) 4=GELU_SPLIT
template<int MODE>
__global__ void __launch_bounds__(512, 1)
gemm_bf3(const __nv_bfloat16* __restrict__ Ah, const __nv_bfloat16* __restrict__ Al,
         const __nv_bfloat16* __restrict__ Bh, const __nv_bfloat16* __restrict__ Bl,
         const float* __restrict__ bias, float* __restrict__ C,
         __nv_bfloat16* __restrict__ oh, __nv_bfloat16* __restrict__ ol,
         const float* __restrict__ pos,
         float* __restrict__ qp, float* __restrict__ kp, float* __restrict__ vp,
         int Nn, int K)
{
    extern __shared__ unsigned char sm[];
    const uint32_t sbase = smem_u32(sm);
    const int tid = threadIdx.x, lane = tid & 31, wid = tid >> 5;
    const int wm = wid & 3, wn = wid >> 2;
    const int bm = blockIdx.y * 128, bn = blockIdx.x * 256;
    const int nc = K >> 5;

    auto load_stage = [&](int buf, int chunk) {
        const int k0 = chunk * 32;
        const uint32_t sb = sbase + buf * STAGE_SB;
        {
            int r = tid >> 2, seg = tid & 3;
            const __nv_bfloat16* gA = Ah + (size_t)(bm + r) * K + k0 + seg * 8;
            uint32_t s = sb + r * ROWB + seg * 16;
            asm volatile("cp.async.cg.shared.global [%0], [%1], 16;" :: "r"(s), "l"(gA));
            const __nv_bfloat16* gA2 = Al + (size_t)(bm + r) * K + k0 + seg * 8;
            asm volatile("cp.async.cg.shared.global [%0], [%1], 16;" :: "r"(s + OFF_AL), "l"(gA2));
        }
#pragma unroll
        for (int j = 0; j < 2; j++) {
            int idx = tid + 512 * j;
            int r = idx >> 2, seg = idx & 3;
            const __nv_bfloat16* gB = Bh + (size_t)(bn + r) * K + k0 + seg * 8;
            uint32_t s = sb + OFF_BH + r * ROWB + seg * 16;
            asm volatile("cp.async.cg.shared.global [%0], [%1], 16;" :: "r"(s), "l"(gB));
            const __nv_bfloat16* gB2 = Bl + (size_t)(bn + r) * K + k0 + seg * 8;
            asm volatile("cp.async.cg.shared.global [%0], [%1], 16;" :: "r"(s + 20480), "l"(gB2));
        }
        asm volatile("cp.async.commit_group;");
    };

    float acc[2][8][4] = {};

    load_stage(0, 0);
    load_stage(1, 1);
    asm volatile("cp.async.wait_group 1;");
    __syncthreads();

    const uint32_t brow = ((lane >> 4) << 3) + (lane & 7);
    for (int c = 0; c < nc; c++) {
        const uint32_t sb = sbase + (c & 1) * STAGE_SB;
#pragma unroll
        for (int k16 = 0; k16 < 2; k16++) {
            uint32_t bh[8][2], bl[8][2];
            const uint32_t bcol = k16 * 32 + ((lane >> 3) & 1) * 16;
#pragma unroll
            for (int ntp = 0; ntp < 4; ntp++) {
                uint32_t bd = sb + OFF_BH + (wn * 64 + ntp * 16 + brow) * ROWB + bcol;
                ldsm4(bh[2*ntp][0], bh[2*ntp][1], bh[2*ntp+1][0], bh[2*ntp+1][1], bd);
                ldsm4(bl[2*ntp][0], bl[2*ntp][1], bl[2*ntp+1][0], bl[2*ntp+1][1], bd + 20480);
            }
            const uint32_t acol = k16 * 32 + (lane >> 4) * 16;
#pragma unroll
            for (int mt = 0; mt < 2; mt++) {
                uint32_t ah4[4], al4[4];
                uint32_t ad = sb + (wm * 32 + mt * 16 + (lane & 15)) * ROWB + acol;
                ldsm4(ah4[0], ah4[1], ah4[2], ah4[3], ad);
                ldsm4(al4[0], al4[1], al4[2], al4[3], ad + OFF_AL);
#pragma unroll
                for (int nt = 0; nt < 8; nt++) {
                    mma16816(acc[mt][nt], ah4, bh[nt]);
                    mma16816(acc[mt][nt], ah4, bl[nt]);
                    mma16816(acc[mt][nt], al4, bh[nt]);
                }
            }
        }
        __syncthreads();
        if (c + 2 < nc) load_stage(c & 1, c + 2);
        asm volatile("cp.async.wait_group 1;");
        __syncthreads();
    }

    // epilogue
    const int tr = lane >> 2, tc = (lane & 3) * 2;
#pragma unroll
    for (int mt = 0; mt < 2; mt++) {
        const int rb = bm + wm * 32 + mt * 16 + tr;
#pragma unroll
        for (int nt = 0; nt < 8; nt++) {
            const int c0 = bn + wn * 64 + nt * 8 + tc;
            const float b0 = bias[c0], b1 = bias[c0 + 1];
#pragma unroll
            for (int hrow = 0; hrow < 2; hrow++) {
                const int r = rb + hrow * 8;
                float v0 = acc[mt][nt][2 * hrow]     + b0;
                float v1 = acc[mt][nt][2 * hrow + 1] + b1;
                if (MODE == 1) {
                    const float2 pp = *reinterpret_cast<const float2*>(&pos[(size_t)(r & 511) * CC + c0]);
                    float2 o = { v0 + pp.x, v1 + pp.y };
                    *reinterpret_cast<float2*>(&C[(size_t)r * CC + c0]) = o;
                } else if (MODE == 2) {
                    const int which = c0 >> 10, ci = c0 & 1023;
                    const int head = ci >> 6, hd = ci & 63;
                    const int bb = r >> 9, n = r & 511;
                    const int bh_ = bb * HH + head;
                    if (which == 0) {
                        float2 o = { v0 * 0.125f, v1 * 0.125f };
                        *reinterpret_cast<float2*>(&qp[((size_t)bh_ * NN + n) * HD + hd]) = o;
                    } else if (which == 1) {
                        float2 o = { v0, v1 };
                        *reinterpret_cast<float2*>(&kp[((size_t)bh_ * NN + n) * HD + hd]) = o;
                    } else {
                        vp[((size_t)bh_ * HD + hd) * NN + n] = v0;
                        vp[((size_t)bh_ * HD + hd + 1) * NN + n] = v1;
                    }
                } else if (MODE == 3) {
                    float2* p = reinterpret_cast<float2*>(&C[(size_t)r * Nn + c0]);
                    float2 old = *p;
                    old.x += v0; old.y += v1;
                    *p = old;
                } else { // GELU_SPLIT
                    float gA = gelu1(v0), gB = gelu1(v1);
                    __nv_bfloat16 h0, l0, h1, l1;
                    split1(gA, h0, l0); split1(gB, h1, l1);
                    __nv_bfloat162 hh; hh.x = h0; hh.y = h1;
                    __nv_bfloat162 ll; ll.x = l0; ll.y = l1;
                    *reinterpret_cast<__nv_bfloat162*>(&oh[(size_t)r * Nn + c0]) = hh;
                    *reinterpret_cast<__nv_bfloat162*>(&ol[(size_t)r * Nn + c0]) = ll;
                }
            }
        }
    }
}

// ---- f32x2 NT GEMM (attention) ----
__device__ __forceinline__ unsigned long long pack2(float x, float y) {
    unsigned long long r;
    asm("mov.b64 %0, {%1, %2};" : "=l"(r) : "f"(x), "f"(y));
    return r;
}
__device__ __forceinline__ void fma2(unsigned long long& d, unsigned long long a, unsigned long long b) {
    asm("fma.rn.f32x2 %0, %1, %2, %0;" : "+l"(d) : "l"(a), "l"(b));
}
union U64F2 { unsigned long long u; float2 f; };

template<int BN_, bool SPLITOUT>
__global__ void __launch_bounds__(256, 2)
gemm_nt(const float* __restrict__ A, const float* __restrict__ W,
        float* __restrict__ C, __nv_bfloat16* __restrict__ oh, __nv_bfloat16* __restrict__ ol,
        int M, int Nn, int K,
        unsigned long long sAz, unsigned long long sBz, unsigned long long sCz)
{
    constexpr int TN = BN_ / 16, LDA = 132, LDB = BN_ + 4, AI = 8, BI = BN_ / 16;
    __shared__ float As[16][LDA];
    __shared__ float Bs[16][LDB];
    const int z = blockIdx.z;
    A += (unsigned long long)z * sAz; W += (unsigned long long)z * sBz; C += (unsigned long long)z * sCz;
    const int bm = blockIdx.y * 128, bn = blockIdx.x * BN_;
    const int tid = threadIdx.x;
    const int lk = tid & 15, lr = tid >> 4, tx = tid & 15, ty = tid >> 4;
    const float* Aptr = A + (size_t)(bm + lr) * K + lk;
    const float* Wptr = W + (size_t)(bn + lr) * K + lk;
    float pa[AI], pb[BI];
#pragma unroll
    for (int i = 0; i < AI; i++) pa[i] = Aptr[(size_t)(16 * i) * K];
#pragma unroll
    for (int i = 0; i < BI; i++) pb[i] = Wptr[(size_t)(16 * i) * K];
    unsigned long long acc[8][TN / 2] = {};
    for (int k0 = 0; k0 < K; k0 += 16) {
#pragma unroll
        for (int i = 0; i < AI; i++) As[lk][lr + 16 * i] = pa[i];
#pragma unroll
        for (int i = 0; i < BI; i++) Bs[lk][lr + 16 * i] = pb[i];
        __syncthreads();
        if (k0 + 16 < K) {
            Aptr += 16; Wptr += 16;
#pragma unroll
            for (int i = 0; i < AI; i++) pa[i] = Aptr[(size_t)(16 * i) * K];
#pragma unroll
            for (int i = 0; i < BI; i++) pb[i] = Wptr[(size_t)(16 * i) * K];
        }
#pragma unroll
        for (int kk = 0; kk < 16; kk++) {
            float4 a0 = *reinterpret_cast<const float4*>(&As[kk][ty * 8]);
            float4 a1 = *reinterpret_cast<const float4*>(&As[kk][ty * 8 + 4]);
            float av[8] = {a0.x, a0.y, a0.z, a0.w, a1.x, a1.y, a1.z, a1.w};
            unsigned long long bb[TN / 2];
            const unsigned long long* bp = reinterpret_cast<const unsigned long long*>(&Bs[kk][tx * TN]);
#pragma unroll
            for (int jp = 0; jp < TN / 2; jp++) bb[jp] = bp[jp];
#pragma unroll
            for (int i = 0; i < 8; i++) {
                unsigned long long a2 = pack2(av[i], av[i]);
#pragma unroll
                for (int jp = 0; jp < TN / 2; jp++) fma2(acc[i][jp], a2, bb[jp]);
            }
        }
        __syncthreads();
    }
#pragma unroll
    for (int i = 0; i < 8; i++) {
        const int m = bm + ty * 8 + i;
#pragma unroll
        for (int jp = 0; jp < TN / 2; jp++) {
            U64F2 u; u.u = acc[i][jp];
            const int n = bn + tx * TN + 2 * jp;
            if (SPLITOUT) {
                const int b = z >> 4, head = z & 15;
                size_t off = ((size_t)(b * NN + m)) * CC + head * HD + n;
                __nv_bfloat16 h0, l0, h1, l1;
                split1(u.f.x, h0, l0); split1(u.f.y, h1, l1);
                __nv_bfloat162 hh; hh.x = h0; hh.y = h1;
                __nv_bfloat162 ll; ll.x = l0; ll.y = l1;
                *reinterpret_cast<__nv_bfloat162*>(&oh[off]) = hh;
                *reinterpret_cast<__nv_bfloat162*>(&ol[off]) = ll;
            } else {
                *reinterpret_cast<float2*>(&C[(size_t)m * Nn + n]) = u.f;
            }
        }
    }
}

// ---- reductions / elementwise ----
template<bool MAXRED>
__device__ __forceinline__ float blockReduce(float val) {
    __shared__ float sh[32];
    __syncthreads();
#pragma unroll
    for (int o = 16; o > 0; o >>= 1) {
        float t = __shfl_xor_sync(0xffffffffu, val, o);
        val = MAXRED ? fmaxf(val, t) : val + t;
    }
    int w = threadIdx.x >> 5, l = threadIdx.x & 31;
    if (l == 0) sh[w] = val;
    __syncthreads();
    int nw = blockDim.x >> 5;
    if (threadIdx.x < 32) {
        val = (l < nw) ? sh[l] : (MAXRED ? -3.4e38f : 0.0f);
#pragma unroll
        for (int o = 16; o > 0; o >>= 1) {
            float t = __shfl_xor_sync(0xffffffffu, val, o);
            val = MAXRED ? fmaxf(val, t) : val + t;
        }
        if (l == 0) sh[0] = val;
    }
    __syncthreads();
    return sh[0];
}

__global__ void layernorm_split_k(const float* __restrict__ x, const float* __restrict__ g,
                                  const float* __restrict__ b,
                                  __nv_bfloat16* __restrict__ oh, __nv_bfloat16* __restrict__ ol)
{
    int row = blockIdx.x, tid = threadIdx.x;
    const float* xr = x + (size_t)row * CC;
    float v[4];
#pragma unroll
    for (int i = 0; i < 4; i++) v[i] = xr[tid + 256 * i];
    float s = blockReduce<false>(v[0] + v[1] + v[2] + v[3]);
    float mu = s * (1.0f / CC);
    float d0 = v[0]-mu, d1 = v[1]-mu, d2 = v[2]-mu, d3 = v[3]-mu;
    float s2 = blockReduce<false>(d0*d0 + d1*d1 + d2*d2 + d3*d3);
    float inv = rsqrtf(s2 * (1.0f / CC) + 1e-6f);
#pragma unroll
    for (int i = 0; i < 4; i++) {
        int c = tid + 256 * i;
        float r = (v[i] - mu) * inv * g[c] + b[c];
        __nv_bfloat16 hh, lo; split1(r, hh, lo);
        oh[(size_t)row * CC + c] = hh;
        ol[(size_t)row * CC + c] = lo;
    }
}

// warp-per-row softmax (scale already folded into q)
__global__ void softmax_k(float* __restrict__ S, const int* __restrict__ mask)
{
    const int gw = (blockIdx.x * blockDim.x + threadIdx.x) >> 5;
    const int lane = threadIdx.x & 31;
    const int b = gw >> 13;
    float* row = S + (size_t)gw * NN;
    const int* mrow = mask + b * NN;
    float v[16];
#pragma unroll
    for (int i = 0; i < 16; i++) {
        int k = lane + 32 * i;
        float t = row[k];
        if (mrow[k] == 0) t = -1e9f;
        v[i] = t;
    }
    float m = v[0];
#pragma unroll
    for (int i = 1; i < 16; i++) m = fmaxf(m, v[i]);
#pragma unroll
    for (int o = 16; o > 0; o >>= 1) m = fmaxf(m, __shfl_xor_sync(0xffffffffu, m, o));
    float s = 0.0f;
#pragma unroll
    for (int i = 0; i < 16; i++) { v[i] = expf(v[i] - m); s += v[i]; }
#pragma unroll
    for (int o = 16; o > 0; o >>= 1) s += __shfl_xor_sync(0xffffffffu, s, o);
    float inv = 1.0f / s;
#pragma unroll
    for (int i = 0; i < 16; i++) row[lane + 32 * i] = v[i] * inv;
}

__global__ void split_k(const float* __restrict__ s, __nv_bfloat16* __restrict__ h,
                        __nv_bfloat16* __restrict__ l, int n) {
    int i = blockIdx.x * blockDim.x + threadIdx.x;
    if (i < n) { __nv_bfloat16 hh, lo; split1(s[i], hh, lo); h[i] = hh; l[i] = lo; }
}
__global__ void final_k(const float* __restrict__ x, const float* __restrict__ Wout,
                        const float* __restrict__ bout, float* __restrict__ out) {
    int m = blockIdx.x, j = threadIdx.x >> 5, lane = threadIdx.x & 31;
    const float* xr = x + (size_t)m * CC;
    const float* w  = Wout + (size_t)j * CC;
    float s = 0.0f;
#pragma unroll
    for (int t = 0; t < CC / 32; t++) s += xr[lane + 32 * t] * w[lane + 32 * t];
#pragma unroll
    for (int o = 16; o > 0; o >>= 1) s += __shfl_xor_sync(0xffffffffu, s, o);
    if (lane == 0) out[m * OUTD + j] = 1.0f / (1.0f + expf(-(s + bout[j])));
}

// ---- host ----
static inline dim3 eg(int total) { return dim3((total + 255) / 256); }

extern "C" void kernel_launch(void* const* d_in, const int* in_sizes, int n_in,
                              void* d_out, int out_size)
{
    (void)in_sizes; (void)n_in; (void)out_size;
    const float* inputs = (const float*)d_in[0];
    const int*   mask   = (const int*)  d_in[1];
    const float* pos    = (const float*)d_in[2];
    const float* Wi     = (const float*)d_in[3];
    const float* bi     = (const float*)d_in[4];
    const float* ln1_g  = (const float*)d_in[5];
    const float* ln1_b  = (const float*)d_in[6];
    const float* Wqkv   = (const float*)d_in[7];
    const float* bqkv   = (const float*)d_in[8];
    const float* Wo     = (const float*)d_in[9];
    const float* bo     = (const float*)d_in[10];
    const float* ln2_g  = (const float*)d_in[11];
    const float* ln2_b  = (const float*)d_in[12];
    const float* W1     = (const float*)d_in[13];
    const float* b1     = (const float*)d_in[14];
    const float* W2     = (const float*)d_in[15];
    const float* b2     = (const float*)d_in[16];
    const float* Wout   = (const float*)d_in[17];
    const float* bout   = (const float*)d_in[18];

    float *x, *q, *k, *vT, *S;
    __nv_bfloat16 *ah, *al, *fh, *fl, *wh, *wl;
    cudaGetSymbolAddress((void**)&x,  g_x);
    cudaGetSymbolAddress((void**)&q,  g_q);
    cudaGetSymbolAddress((void**)&k,  g_k);
    cudaGetSymbolAddress((void**)&vT, g_vT);
    cudaGetSymbolAddress((void**)&S,  g_S);
    cudaGetSymbolAddress((void**)&ah, g_ah);
    cudaGetSymbolAddress((void**)&al, g_al);
    cudaGetSymbolAddress((void**)&fh, g_fh);
    cudaGetSymbolAddress((void**)&fl, g_fl);
    cudaGetSymbolAddress((void**)&wh, g_wh);
    cudaGetSymbolAddress((void**)&wl, g_wl);

    cudaFuncSetAttribute(gemm_bf3<1>, cudaFuncAttributeMaxDynamicSharedMemorySize, DYN_SB);
    cudaFuncSetAttribute(gemm_bf3<2>, cudaFuncAttributeMaxDynamicSharedMemorySize, DYN_SB);
    cudaFuncSetAttribute(gemm_bf3<3>, cudaFuncAttributeMaxDynamicSharedMemorySize, DYN_SB);
    cudaFuncSetAttribute(gemm_bf3<4>, cudaFuncAttributeMaxDynamicSharedMemorySize, DYN_SB);

    const int tot_xc = MM * CC;

    // split weights to bf16 hi/lo
    split_k<<<eg(CC * CC), 256>>>(Wi,   wh + OFF_WI,   wl + OFF_WI,   CC * CC);
    split_k<<<eg(LL*3*CC*CC), 256>>>(Wqkv, wh + OFF_WQKV, wl + OFF_WQKV, LL*3*CC*CC);
    split_k<<<eg(LL*CC*CC), 256>>>(Wo,  wh + OFF_WO,   wl + OFF_WO,   LL*CC*CC);
    split_k<<<eg(LL*FF*CC), 256>>>(W1,  wh + OFF_W1,   wl + OFF_W1,   LL*FF*CC);
    split_k<<<eg(LL*CC*FF), 256>>>(W2,  wh + OFF_W2,   wl + OFF_W2,   LL*CC*FF);

    // x = inputs @ Wi.T + bi + pos   (fused)
    split_k<<<eg(tot_xc), 256>>>(inputs, ah, al, tot_xc);
    gemm_bf3<1><<<dim3(CC/256, MM/128), 512, DYN_SB>>>(
        ah, al, wh + OFF_WI, wl + OFF_WI, bi, x, nullptr, nullptr, pos,
        nullptr, nullptr, nullptr, CC, CC);

    for (int l = 0; l < LL; l++) {
        const size_t oq = OFF_WQKV + (size_t)l * 3 * CC * CC;
        const size_t oo = OFF_WO   + (size_t)l * CC * CC;
        const size_t o1 = OFF_W1   + (size_t)l * FF * CC;
        const size_t o2 = OFF_W2   + (size_t)l * CC * FF;

        layernorm_split_k<<<MM, 256>>>(x, ln1_g + l * CC, ln1_b + l * CC, ah, al);
        // qkv gemm fused scatter (q pre-scaled by 1/8)
        gemm_bf3<2><<<dim3(3*CC/256, MM/128), 512, DYN_SB>>>(
            ah, al, wh + oq, wl + oq, bqkv + (size_t)l * 3 * CC, nullptr,
            nullptr, nullptr, nullptr, q, k, vT, 3 * CC, CC);

        gemm_nt<128,false><<<dim3(NN/128, NN/128, BHN), 256>>>(q, k, S, nullptr, nullptr,
            NN, NN, HD,
            (unsigned long long)NN*HD, (unsigned long long)NN*HD, (unsigned long long)NN*NN);
        softmax_k<<<BHN * NN / 8, 256>>>(S, mask);
        // O = S @ vT.T, fused reshape + bf16 split into ah/al
        gemm_nt<64,true><<<dim3(HD/64, NN/128, BHN), 256>>>(S, vT, nullptr, ah, al,
            NN, HD, NN,
            (unsigned long long)NN*NN, (unsigned long long)HD*NN, 0ULL);

        // x += o @ Wo.T + bo  (fused residual)
        gemm_bf3<3><<<dim3(CC/256, MM/128), 512, DYN_SB>>>(
            ah, al, wh + oo, wl + oo, bo + (size_t)l * CC, x,
            nullptr, nullptr, nullptr, nullptr, nullptr, nullptr, CC, CC);

        layernorm_split_k<<<MM, 256>>>(x, ln2_g + l * CC, ln2_b + l * CC, ah, al);
        // f = gelu(h @ W1.T + b1) fused split -> fh/fl
        gemm_bf3<4><<<dim3(FF/256, MM/128), 512, DYN_SB>>>(
            ah, al, wh + o1, wl + o1, b1 + (size_t)l * FF, nullptr,
            fh, fl, nullptr, nullptr, nullptr, nullptr, FF, CC);
        // x += f @ W2.T + b2  (fused residual)
        gemm_bf3<3><<<dim3(CC/256, MM/128), 512, DYN_SB>>>(
            fh, fl, wh + o2, wl + o2, b2 + (size_t)l * CC, x,
            nullptr, nullptr, nullptr, nullptr, nullptr, nullptr, CC, FF);
    }

    final_k<<<MM, 64>>>(x, Wout, bout, (float*)d_out);
}

// round 12
// speedup vs baseline: 2.0998x; 1.0622x over previous
#include <cuda_runtime.h>
#include <cuda_bf16.h>
#include <math.h>
#include <stdint.h>

#define BB 8
#define NN 512
#define CC 1024
#define HH 16
#define HD 64
#define LL 6
#define FF 4096
#define OUTD 2
#define MM (BB*NN)
#define BHN (BB*HH)
#define LOG2E 1.44269504088896f

// gemm_bf3 tiling: 128x256x32, 512 threads (4m x 4n warps, warp tile 32x64)
#define ROWB 80
#define OFF_AL 10240
#define OFF_BH 20480
#define STAGE_SB 61440
#define DYN_SB (2*STAGE_SB)

// weight hi/lo offsets (elements)
#define OFF_WI   0ULL
#define OFF_WQKV 1048576ULL
#define OFF_WO   19922944ULL
#define OFF_W1   26214400ULL
#define OFF_W2   51380224ULL
#define WELEMS   76546048ULL

// flash smem
#define FLD 68
#define FLASH_SB (4*64*FLD*4)   // 69632

// ---- scratch ----
__device__ float g_x [MM*CC];
__device__ float g_q [BHN*NN*HD];
__device__ float g_k [BHN*NN*HD];
__device__ float g_v [BHN*NN*HD];
__device__ __nv_bfloat16 g_ah[MM*CC];
__device__ __nv_bfloat16 g_al[MM*CC];
__device__ __nv_bfloat16 g_fh[MM*FF];
__device__ __nv_bfloat16 g_fl[MM*FF];
__device__ __nv_bfloat16 g_wh[WELEMS];
__device__ __nv_bfloat16 g_wl[WELEMS];

__device__ __forceinline__ uint32_t smem_u32(const void* p) {
    uint32_t a;
    asm("{ .reg .u64 t; cvta.to.shared.u64 t, %1; cvt.u32.u64 %0, t; }" : "=r"(a) : "l"(p));
    return a;
}
__device__ __forceinline__ void ldsm4(uint32_t& r0, uint32_t& r1, uint32_t& r2, uint32_t& r3, uint32_t a) {
    asm volatile("ldmatrix.sync.aligned.m8n8.x4.shared.b16 {%0,%1,%2,%3},[%4];"
                 : "=r"(r0), "=r"(r1), "=r"(r2), "=r"(r3) : "r"(a));
}
__device__ __forceinline__ void mma16816(float* c, const uint32_t* a, const uint32_t* b) {
    asm volatile(
        "mma.sync.aligned.m16n8k16.row.col.f32.bf16.bf16.f32 "
        "{%0,%1,%2,%3},{%4,%5,%6,%7},{%8,%9},{%0,%1,%2,%3};"
        : "+f"(c[0]), "+f"(c[1]), "+f"(c[2]), "+f"(c[3])
        : "r"(a[0]), "r"(a[1]), "r"(a[2]), "r"(a[3]), "r"(b[0]), "r"(b[1]));
}
__device__ __forceinline__ void split1(float v, __nv_bfloat16& h, __nv_bfloat16& l) {
    h = __float2bfloat16_rn(v);
    l = __float2bfloat16_rn(v - __bfloat162float(h));
}
__device__ __forceinline__ float gelu1(float v) {
    return 0.5f * v * (1.0f + erff(v * 0.70710678118654752f));
}
__device__ __forceinline__ unsigned long long pack2(float x, float y) {
    unsigned long long r;
    asm("mov.b64 %0, {%1, %2};" : "=l"(r) : "f"(x), "f"(y));
    return r;
}
__device__ __forceinline__ void fma2(unsigned long long& d, unsigned long long a, unsigned long long b) {
    asm("fma.rn.f32x2 %0, %1, %2, %0;" : "+l"(d) : "l"(a), "l"(b));
}
__device__ __forceinline__ void mul2(unsigned long long& d, unsigned long long a) {
    asm("mul.rn.f32x2 %0, %0, %1;" : "+l"(d) : "l"(a));
}
union U64F2 { unsigned long long u; float2 f; };

// MODE: 1=OUT_POS 2=QKV scatter 3=RESID 4=GELU_SPLIT
template<int MODE>
__global__ void __launch_bounds__(512, 1)
gemm_bf3(const __nv_bfloat16* __restrict__ Ah, const __nv_bfloat16* __restrict__ Al,
         const __nv_bfloat16* __restrict__ Bh, const __nv_bfloat16* __restrict__ Bl,
         const float* __restrict__ bias, float* __restrict__ C,
         __nv_bfloat16* __restrict__ oh, __nv_bfloat16* __restrict__ ol,
         const float* __restrict__ pos,
         float* __restrict__ qp, float* __restrict__ kp, float* __restrict__ vp,
         int Nn, int K)
{
    extern __shared__ unsigned char sm[];
    const uint32_t sbase = smem_u32(sm);
    const int tid = threadIdx.x, lane = tid & 31, wid = tid >> 5;
    const int wm = wid & 3, wn = wid >> 2;
    const int bm = blockIdx.y * 128, bn = blockIdx.x * 256;
    const int nc = K >> 5;

    auto load_stage = [&](int buf, int chunk) {
        const int k0 = chunk * 32;
        const uint32_t sb = sbase + buf * STAGE_SB;
        {
            int r = tid >> 2, seg = tid & 3;
            const __nv_bfloat16* gA = Ah + (size_t)(bm + r) * K + k0 + seg * 8;
            uint32_t s = sb + r * ROWB + seg * 16;
            asm volatile("cp.async.cg.shared.global [%0], [%1], 16;" :: "r"(s), "l"(gA));
            const __nv_bfloat16* gA2 = Al + (size_t)(bm + r) * K + k0 + seg * 8;
            asm volatile("cp.async.cg.shared.global [%0], [%1], 16;" :: "r"(s + OFF_AL), "l"(gA2));
        }
#pragma unroll
        for (int j = 0; j < 2; j++) {
            int idx = tid + 512 * j;
            int r = idx >> 2, seg = idx & 3;
            const __nv_bfloat16* gB = Bh + (size_t)(bn + r) * K + k0 + seg * 8;
            uint32_t s = sb + OFF_BH + r * ROWB + seg * 16;
            asm volatile("cp.async.cg.shared.global [%0], [%1], 16;" :: "r"(s), "l"(gB));
            const __nv_bfloat16* gB2 = Bl + (size_t)(bn + r) * K + k0 + seg * 8;
            asm volatile("cp.async.cg.shared.global [%0], [%1], 16;" :: "r"(s + 20480), "l"(gB2));
        }
        asm volatile("cp.async.commit_group;");
    };

    float acc[2][8][4] = {};

    load_stage(0, 0);
    load_stage(1, 1);
    asm volatile("cp.async.wait_group 1;");
    __syncthreads();

    const uint32_t brow = ((lane >> 4) << 3) + (lane & 7);
    for (int c = 0; c < nc; c++) {
        const uint32_t sb = sbase + (c & 1) * STAGE_SB;
#pragma unroll
        for (int k16 = 0; k16 < 2; k16++) {
            uint32_t bh[8][2], bl[8][2];
            const uint32_t bcol = k16 * 32 + ((lane >> 3) & 1) * 16;
#pragma unroll
            for (int ntp = 0; ntp < 4; ntp++) {
                uint32_t bd = sb + OFF_BH + (wn * 64 + ntp * 16 + brow) * ROWB + bcol;
                ldsm4(bh[2*ntp][0], bh[2*ntp][1], bh[2*ntp+1][0], bh[2*ntp+1][1], bd);
                ldsm4(bl[2*ntp][0], bl[2*ntp][1], bl[2*ntp+1][0], bl[2*ntp+1][1], bd + 20480);
            }
            const uint32_t acol = k16 * 32 + (lane >> 4) * 16;
#pragma unroll
            for (int mt = 0; mt < 2; mt++) {
                uint32_t ah4[4], al4[4];
                uint32_t ad = sb + (wm * 32 + mt * 16 + (lane & 15)) * ROWB + acol;
                ldsm4(ah4[0], ah4[1], ah4[2], ah4[3], ad);
                ldsm4(al4[0], al4[1], al4[2], al4[3], ad + OFF_AL);
                // separated product loops: same-acc HMMAs 8 apart (break RAW chains)
#pragma unroll
                for (int nt = 0; nt < 8; nt++) mma16816(acc[mt][nt], ah4, bh[nt]);
#pragma unroll
                for (int nt = 0; nt < 8; nt++) mma16816(acc[mt][nt], ah4, bl[nt]);
#pragma unroll
                for (int nt = 0; nt < 8; nt++) mma16816(acc[mt][nt], al4, bh[nt]);
            }
        }
        __syncthreads();
        if (c + 2 < nc) load_stage(c & 1, c + 2);
        asm volatile("cp.async.wait_group 1;");
        __syncthreads();
    }

    const int tr = lane >> 2, tc = (lane & 3) * 2;
#pragma unroll
    for (int mt = 0; mt < 2; mt++) {
        const int rb = bm + wm * 32 + mt * 16 + tr;
#pragma unroll
        for (int nt = 0; nt < 8; nt++) {
            const int c0 = bn + wn * 64 + nt * 8 + tc;
            const float b0 = bias[c0], b1 = bias[c0 + 1];
#pragma unroll
            for (int hrow = 0; hrow < 2; hrow++) {
                const int r = rb + hrow * 8;
                float v0 = acc[mt][nt][2 * hrow]     + b0;
                float v1 = acc[mt][nt][2 * hrow + 1] + b1;
                if (MODE == 1) {
                    const float2 pp = *reinterpret_cast<const float2*>(&pos[(size_t)(r & 511) * CC + c0]);
                    float2 o = { v0 + pp.x, v1 + pp.y };
                    *reinterpret_cast<float2*>(&C[(size_t)r * CC + c0]) = o;
                } else if (MODE == 2) {
                    const int which = c0 >> 10, ci = c0 & 1023;
                    const int head = ci >> 6, hd = ci & 63;
                    const int bb = r >> 9, n = r & 511;
                    const size_t off = ((size_t)(bb * HH + head) * NN + n) * HD + hd;
                    if (which == 0) {
                        float2 o = { v0 * 0.125f, v1 * 0.125f };
                        *reinterpret_cast<float2*>(&qp[off]) = o;
                    } else if (which == 1) {
                        float2 o = { v0, v1 };
                        *reinterpret_cast<float2*>(&kp[off]) = o;
                    } else {
                        float2 o = { v0, v1 };
                        *reinterpret_cast<float2*>(&vp[off]) = o;
                    }
                } else if (MODE == 3) {
                    float2* p = reinterpret_cast<float2*>(&C[(size_t)r * Nn + c0]);
                    float2 old = *p;
                    old.x += v0; old.y += v1;
                    *p = old;
                } else {
                    float gA = gelu1(v0), gB = gelu1(v1);
                    __nv_bfloat16 h0, l0, h1, l1;
                    split1(gA, h0, l0); split1(gB, h1, l1);
                    __nv_bfloat162 hh; hh.x = h0; hh.y = h1;
                    __nv_bfloat162 ll; ll.x = l0; ll.y = l1;
                    *reinterpret_cast<__nv_bfloat162*>(&oh[(size_t)r * Nn + c0]) = hh;
                    *reinterpret_cast<__nv_bfloat162*>(&ol[(size_t)r * Nn + c0]) = ll;
                }
            }
        }
    }
}

// ---- fused flash attention (f32x2): per block 64 q-rows x all 512 keys ----
// q pre-scaled by 1/8. Output written reshaped + bf16-split to oh/ol.
__global__ void __launch_bounds__(256, 2)
flash_k(const float* __restrict__ q, const float* __restrict__ k, const float* __restrict__ v,
        const int* __restrict__ mask,
        __nv_bfloat16* __restrict__ oh, __nv_bfloat16* __restrict__ ol)
{
    extern __shared__ float fs[];
    float* QsT = fs;                 // [64 kk][FLD]
    float* KsT = fs + 64 * FLD;      // [64 kk][FLD]
    float* Vs  = fs + 2 * 64 * FLD;  // [64 key][FLD]
    float* PsT = fs + 3 * 64 * FLD;  // [64 key][FLD] (P transposed: [key][qrow])
    __shared__ int msk[64];

    const int tid = threadIdx.x, tx = tid & 15, ty = tid >> 4;
    const int bh = blockIdx.y, b = bh >> 4, head = bh & 15;
    const int q0 = blockIdx.x * 64;
    const float* qbase = q + ((size_t)bh * NN + q0) * HD;
    const float* kbase = k + (size_t)bh * NN * HD;
    const float* vbase = v + (size_t)bh * NN * HD;

    // load Q transposed: QsT[hd][row]
#pragma unroll
    for (int i = 0; i < 4; i++) {
        int idx = tid + 256 * i;
        int row = idx >> 4, c4 = (idx & 15) * 4;
        float4 qq = *reinterpret_cast<const float4*>(qbase + row * HD + c4);
        QsT[(c4 + 0) * FLD + row] = qq.x;
        QsT[(c4 + 1) * FLD + row] = qq.y;
        QsT[(c4 + 2) * FLD + row] = qq.z;
        QsT[(c4 + 3) * FLD + row] = qq.w;
    }

    unsigned long long O2[4][2] = {};
    float m[4] = {-3.0e38f, -3.0e38f, -3.0e38f, -3.0e38f};
    float l[4] = {};

    for (int kc = 0; kc < 8; kc++) {
        __syncthreads();   // prior-iteration readers of KsT/Vs/PsT done; QsT ready on first iter
#pragma unroll
        for (int i = 0; i < 4; i++) {
            int idx = tid + 256 * i;
            int row = idx >> 4, c4 = (idx & 15) * 4;
            float4 kk4 = *reinterpret_cast<const float4*>(kbase + (size_t)(kc * 64 + row) * HD + c4);
            KsT[(c4 + 0) * FLD + row] = kk4.x;
            KsT[(c4 + 1) * FLD + row] = kk4.y;
            KsT[(c4 + 2) * FLD + row] = kk4.z;
            KsT[(c4 + 3) * FLD + row] = kk4.w;
            float4 vv4 = *reinterpret_cast<const float4*>(vbase + (size_t)(kc * 64 + row) * HD + c4);
            *reinterpret_cast<float4*>(Vs + row * FLD + c4) = vv4;
        }
        if (tid < 64) msk[tid] = mask[b * NN + kc * 64 + tid];
        __syncthreads();

        // S chunk = Q @ K^T
        unsigned long long s2[4][2] = {};
        for (int kk = 0; kk < 64; kk++) {
            float4 q4 = *reinterpret_cast<float4*>(QsT + kk * FLD + 4 * ty);
            float4 k4 = *reinterpret_cast<float4*>(KsT + kk * FLD + 4 * tx);
            unsigned long long kp0 = pack2(k4.x, k4.y), kp1 = pack2(k4.z, k4.w);
            float qa[4] = {q4.x, q4.y, q4.z, q4.w};
#pragma unroll
            for (int i = 0; i < 4; i++) {
                unsigned long long qq = pack2(qa[i], qa[i]);
                fma2(s2[i][0], qq, kp0);
                fma2(s2[i][1], qq, kp1);
            }
        }
        float s[4][4];
#pragma unroll
        for (int i = 0; i < 4; i++) {
            U64F2 u0, u1; u0.u = s2[i][0]; u1.u = s2[i][1];
            s[i][0] = u0.f.x; s[i][1] = u0.f.y; s[i][2] = u1.f.x; s[i][3] = u1.f.y;
        }
#pragma unroll
        for (int j = 0; j < 4; j++)
            if (msk[4 * tx + j] == 0) { s[0][j] = -1e9f; s[1][j] = -1e9f; s[2][j] = -1e9f; s[3][j] = -1e9f; }

        // online softmax update
#pragma unroll
        for (int i = 0; i < 4; i++) {
            float cm = fmaxf(fmaxf(s[i][0], s[i][1]), fmaxf(s[i][2], s[i][3]));
#pragma unroll
            for (int o = 8; o > 0; o >>= 1) cm = fmaxf(cm, __shfl_xor_sync(0xffffffffu, cm, o));
            float mn = fmaxf(m[i], cm);
            float corr = exp2f((m[i] - mn) * LOG2E);
            m[i] = mn;
            float rs = 0.0f;
#pragma unroll
            for (int j = 0; j < 4; j++) { s[i][j] = exp2f((s[i][j] - mn) * LOG2E); rs += s[i][j]; }
#pragma unroll
            for (int o = 8; o > 0; o >>= 1) rs += __shfl_xor_sync(0xffffffffu, rs, o);
            l[i] = l[i] * corr + rs;
            unsigned long long cp = pack2(corr, corr);
            mul2(O2[i][0], cp);
            mul2(O2[i][1], cp);
        }
        // P transposed to smem: PsT[key][qrow]
#pragma unroll
        for (int j = 0; j < 4; j++) {
            float4 pv = { s[0][j], s[1][j], s[2][j], s[3][j] };
            *reinterpret_cast<float4*>(PsT + (4 * tx + j) * FLD + 4 * ty) = pv;
        }
        __syncthreads();

        // O += P @ V
        for (int kk = 0; kk < 64; kk++) {
            float4 p4 = *reinterpret_cast<float4*>(PsT + kk * FLD + 4 * ty);
            float4 v4 = *reinterpret_cast<float4*>(Vs + kk * FLD + 4 * tx);
            unsigned long long vp0 = pack2(v4.x, v4.y), vp1 = pack2(v4.z, v4.w);
            float pa[4] = {p4.x, p4.y, p4.z, p4.w};
#pragma unroll
            for (int i = 0; i < 4; i++) {
                unsigned long long pp = pack2(pa[i], pa[i]);
                fma2(O2[i][0], pp, vp0);
                fma2(O2[i][1], pp, vp1);
            }
        }
    }

    // epilogue: normalize, split bf16, store reshaped
#pragma unroll
    for (int i = 0; i < 4; i++) {
        float inv = 1.0f / l[i];
        U64F2 u0, u1; u0.u = O2[i][0]; u1.u = O2[i][1];
        float o0 = u0.f.x * inv, o1 = u0.f.y * inv, o2 = u1.f.x * inv, o3 = u1.f.y * inv;
        __nv_bfloat16 h0, l0, h1, l1, h2, l2, h3, l3;
        split1(o0, h0, l0); split1(o1, h1, l1); split1(o2, h2, l2); split1(o3, h3, l3);
        const size_t off = ((size_t)(b * NN + q0 + 4 * ty + i)) * CC + head * HD + 4 * tx;
        __nv_bfloat162 hA; hA.x = h0; hA.y = h1;
        __nv_bfloat162 hB; hB.x = h2; hB.y = h3;
        __nv_bfloat162 lA; lA.x = l0; lA.y = l1;
        __nv_bfloat162 lB; lB.x = l2; lB.y = l3;
        *reinterpret_cast<__nv_bfloat162*>(&oh[off])     = hA;
        *reinterpret_cast<__nv_bfloat162*>(&oh[off + 2]) = hB;
        *reinterpret_cast<__nv_bfloat162*>(&ol[off])     = lA;
        *reinterpret_cast<__nv_bfloat162*>(&ol[off + 2]) = lB;
    }
}

// ---- reductions / elementwise ----
template<bool MAXRED>
__device__ __forceinline__ float blockReduce(float val) {
    __shared__ float sh[32];
    __syncthreads();
#pragma unroll
    for (int o = 16; o > 0; o >>= 1) {
        float t = __shfl_xor_sync(0xffffffffu, val, o);
        val = MAXRED ? fmaxf(val, t) : val + t;
    }
    int w = threadIdx.x >> 5, ln = threadIdx.x & 31;
    if (ln == 0) sh[w] = val;
    __syncthreads();
    int nw = blockDim.x >> 5;
    if (threadIdx.x < 32) {
        val = (ln < nw) ? sh[ln] : (MAXRED ? -3.4e38f : 0.0f);
#pragma unroll
        for (int o = 16; o > 0; o >>= 1) {
            float t = __shfl_xor_sync(0xffffffffu, val, o);
            val = MAXRED ? fmaxf(val, t) : val + t;
        }
        if (ln == 0) sh[0] = val;
    }
    __syncthreads();
    return sh[0];
}

__global__ void layernorm_split_k(const float* __restrict__ x, const float* __restrict__ g,
                                  const float* __restrict__ b,
                                  __nv_bfloat16* __restrict__ oh, __nv_bfloat16* __restrict__ ol)
{
    int row = blockIdx.x, tid = threadIdx.x;
    const float* xr = x + (size_t)row * CC;
    float4 vv = *reinterpret_cast<const float4*>(xr + tid * 4);
    float s = blockReduce<false>(vv.x + vv.y + vv.z + vv.w);
    float mu = s * (1.0f / CC);
    float d0 = vv.x - mu, d1 = vv.y - mu, d2 = vv.z - mu, d3 = vv.w - mu;
    float s2 = blockReduce<false>(d0*d0 + d1*d1 + d2*d2 + d3*d3);
    float inv = rsqrtf(s2 * (1.0f / CC) + 1e-6f);
    float4 gg = *reinterpret_cast<const float4*>(g + tid * 4);
    float4 bb = *reinterpret_cast<const float4*>(b + tid * 4);
    float r0 = d0 * inv * gg.x + bb.x;
    float r1 = d1 * inv * gg.y + bb.y;
    float r2 = d2 * inv * gg.z + bb.z;
    float r3 = d3 * inv * gg.w + bb.w;
    __nv_bfloat16 h0, l0, h1, l1, h2, l2, h3, l3;
    split1(r0, h0, l0); split1(r1, h1, l1); split1(r2, h2, l2); split1(r3, h3, l3);
    size_t off = (size_t)row * CC + tid * 4;
    __nv_bfloat162 hA; hA.x = h0; hA.y = h1;
    __nv_bfloat162 hB; hB.x = h2; hB.y = h3;
    __nv_bfloat162 lA; lA.x = l0; lA.y = l1;
    __nv_bfloat162 lB; lB.x = l2; lB.y = l3;
    *reinterpret_cast<__nv_bfloat162*>(&oh[off])     = hA;
    *reinterpret_cast<__nv_bfloat162*>(&oh[off + 2]) = hB;
    *reinterpret_cast<__nv_bfloat162*>(&ol[off])     = lA;
    *reinterpret_cast<__nv_bfloat162*>(&ol[off + 2]) = lB;
}

// vectorized x4 split
__global__ void split_k(const float4* __restrict__ s, __nv_bfloat162* __restrict__ h,
                        __nv_bfloat162* __restrict__ l, int n4) {
    int i = blockIdx.x * blockDim.x + threadIdx.x;
    if (i < n4) {
        float4 v = s[i];
        __nv_bfloat16 h0, l0, h1, l1, h2, l2, h3, l3;
        split1(v.x, h0, l0); split1(v.y, h1, l1); split1(v.z, h2, l2); split1(v.w, h3, l3);
        __nv_bfloat162 hA; hA.x = h0; hA.y = h1;
        __nv_bfloat162 hB; hB.x = h2; hB.y = h3;
        __nv_bfloat162 lA; lA.x = l0; lA.y = l1;
        __nv_bfloat162 lB; lB.x = l2; lB.y = l3;
        h[2 * i] = hA; h[2 * i + 1] = hB;
        l[2 * i] = lA; l[2 * i + 1] = lB;
    }
}

__global__ void final_k(const float* __restrict__ x, const float* __restrict__ Wout,
                        const float* __restrict__ bout, float* __restrict__ out) {
    int mrow = blockIdx.x, j = threadIdx.x >> 5, lane = threadIdx.x & 31;
    const float* xr = x + (size_t)mrow * CC;
    const float* w  = Wout + (size_t)j * CC;
    float s = 0.0f;
#pragma unroll
    for (int t = 0; t < CC / 32; t++) s += xr[lane + 32 * t] * w[lane + 32 * t];
#pragma unroll
    for (int o = 16; o > 0; o >>= 1) s += __shfl_xor_sync(0xffffffffu, s, o);
    if (lane == 0) out[mrow * OUTD + j] = 1.0f / (1.0f + expf(-(s + bout[j])));
}

// ---- host ----
static inline dim3 eg4(int total) { return dim3((total / 4 + 255) / 256); }

extern "C" void kernel_launch(void* const* d_in, const int* in_sizes, int n_in,
                              void* d_out, int out_size)
{
    (void)in_sizes; (void)n_in; (void)out_size;
    const float* inputs = (const float*)d_in[0];
    const int*   mask   = (const int*)  d_in[1];
    const float* pos    = (const float*)d_in[2];
    const float* Wi     = (const float*)d_in[3];
    const float* bi     = (const float*)d_in[4];
    const float* ln1_g  = (const float*)d_in[5];
    const float* ln1_b  = (const float*)d_in[6];
    const float* Wqkv   = (const float*)d_in[7];
    const float* bqkv   = (const float*)d_in[8];
    const float* Wo     = (const float*)d_in[9];
    const float* bo     = (const float*)d_in[10];
    const float* ln2_g  = (const float*)d_in[11];
    const float* ln2_b  = (const float*)d_in[12];
    const float* W1     = (const float*)d_in[13];
    const float* b1     = (const float*)d_in[14];
    const float* W2     = (const float*)d_in[15];
    const float* b2     = (const float*)d_in[16];
    const float* Wout   = (const float*)d_in[17];
    const float* bout   = (const float*)d_in[18];

    float *x, *q, *k, *v;
    __nv_bfloat16 *ah, *al, *fh, *fl, *wh, *wl;
    cudaGetSymbolAddress((void**)&x,  g_x);
    cudaGetSymbolAddress((void**)&q,  g_q);
    cudaGetSymbolAddress((void**)&k,  g_k);
    cudaGetSymbolAddress((void**)&v,  g_v);
    cudaGetSymbolAddress((void**)&ah, g_ah);
    cudaGetSymbolAddress((void**)&al, g_al);
    cudaGetSymbolAddress((void**)&fh, g_fh);
    cudaGetSymbolAddress((void**)&fl, g_fl);
    cudaGetSymbolAddress((void**)&wh, g_wh);
    cudaGetSymbolAddress((void**)&wl, g_wl);

    cudaFuncSetAttribute(gemm_bf3<1>, cudaFuncAttributeMaxDynamicSharedMemorySize, DYN_SB);
    cudaFuncSetAttribute(gemm_bf3<2>, cudaFuncAttributeMaxDynamicSharedMemorySize, DYN_SB);
    cudaFuncSetAttribute(gemm_bf3<3>, cudaFuncAttributeMaxDynamicSharedMemorySize, DYN_SB);
    cudaFuncSetAttribute(gemm_bf3<4>, cudaFuncAttributeMaxDynamicSharedMemorySize, DYN_SB);
    cudaFuncSetAttribute(flash_k, cudaFuncAttributeMaxDynamicSharedMemorySize, FLASH_SB);

    const int tot_xc = MM * CC;

    split_k<<<eg4(CC * CC), 256>>>((const float4*)Wi, (__nv_bfloat162*)(wh + OFF_WI),
                                   (__nv_bfloat162*)(wl + OFF_WI), CC * CC / 4);
    split_k<<<eg4(LL*3*CC*CC), 256>>>((const float4*)Wqkv, (__nv_bfloat162*)(wh + OFF_WQKV),
                                      (__nv_bfloat162*)(wl + OFF_WQKV), LL*3*CC*CC/4);
    split_k<<<eg4(LL*CC*CC), 256>>>((const float4*)Wo, (__nv_bfloat162*)(wh + OFF_WO),
                                    (__nv_bfloat162*)(wl + OFF_WO), LL*CC*CC/4);
    split_k<<<eg4(LL*FF*CC), 256>>>((const float4*)W1, (__nv_bfloat162*)(wh + OFF_W1),
                                    (__nv_bfloat162*)(wl + OFF_W1), LL*FF*CC/4);
    split_k<<<eg4(LL*CC*FF), 256>>>((const float4*)W2, (__nv_bfloat162*)(wh + OFF_W2),
                                    (__nv_bfloat162*)(wl + OFF_W2), LL*CC*FF/4);

    // x = inputs @ Wi.T + bi + pos
    split_k<<<eg4(tot_xc), 256>>>((const float4*)inputs, (__nv_bfloat162*)ah,
                                  (__nv_bfloat162*)al, tot_xc / 4);
    gemm_bf3<1><<<dim3(CC/256, MM/128), 512, DYN_SB>>>(
        ah, al, wh + OFF_WI, wl + OFF_WI, bi, x, nullptr, nullptr, pos,
        nullptr, nullptr, nullptr, CC, CC);

    for (int l = 0; l < LL; l++) {
        const size_t oq = OFF_WQKV + (size_t)l * 3 * CC * CC;
        const size_t oo = OFF_WO   + (size_t)l * CC * CC;
        const size_t o1 = OFF_W1   + (size_t)l * FF * CC;
        const size_t o2 = OFF_W2   + (size_t)l * CC * FF;

        layernorm_split_k<<<MM, 256>>>(x, ln1_g + l * CC, ln1_b + l * CC, ah, al);
        gemm_bf3<2><<<dim3(3*CC/256, MM/128), 512, DYN_SB>>>(
            ah, al, wh + oq, wl + oq, bqkv + (size_t)l * 3 * CC, nullptr,
            nullptr, nullptr, nullptr, q, k, v, 3 * CC, CC);

        // fused attention -> writes bf16-split o directly into ah/al
        flash_k<<<dim3(NN/64, BHN), 256, FLASH_SB>>>(q, k, v, mask, ah, al);

        gemm_bf3<3><<<dim3(CC/256, MM/128), 512, DYN_SB>>>(
            ah, al, wh + oo, wl + oo, bo + (size_t)l * CC, x,
            nullptr, nullptr, nullptr, nullptr, nullptr, nullptr, CC, CC);

        layernorm_split_k<<<MM, 256>>>(x, ln2_g + l * CC, ln2_b + l * CC, ah, al);
        gemm_bf3<4><<<dim3(FF/256, MM/128), 512, DYN_SB>>>(
            ah, al, wh + o1, wl + o1, b1 + (size_t)l * FF, nullptr,
            fh, fl, nullptr, nullptr, nullptr, nullptr, FF, CC);
        gemm_bf3<3><<<dim3(CC/256, MM/128), 512, DYN_SB>>>(
            fh, fl, wh + o2, wl + o2, b2 + (size_t)l * CC, x,
            nullptr, nullptr, nullptr, nullptr, nullptr, nullptr, CC, FF);
    }

    final_k<<<MM, 64>>>(x, Wout, bout, (float*)d_out);
}

// round 13
// speedup vs baseline: 2.4624x; 1.1727x over previous
#include <cuda_runtime.h>
#include <cuda_bf16.h>
#include <cuda_fp16.h>
#include <math.h>
#include <stdint.h>

#define BB 8
#define NN 512
#define CC 1024
#define HH 16
#define HD 64
#define LL 6
#define FF 4096
#define OUTD 2
#define MM (BB*NN)
#define BHN (BB*HH)
#define LOG2E 1.44269504088896f

#define ROWB 80
#define OFF_AL 10240
#define OFF_BH 20480
#define STAGE_SB 61440
#define DYN_SB (2*STAGE_SB)

#define OFF_WI   0ULL
#define OFF_WQKV 1048576ULL
#define OFF_WO   19922944ULL
#define OFF_W1   26214400ULL
#define OFF_W2   51380224ULL
#define WELEMS   76546048ULL

#define FLD 68
#define FLASH_SB (4*64*FLD*4)

// ---- scratch ----
__device__ float g_x [MM*CC];
__device__ float g_q [BHN*NN*HD];
__device__ float g_k [BHN*NN*HD];
__device__ float g_v [BHN*NN*HD];
__device__ __half        g_ah[MM*CC];
__device__ __nv_bfloat16 g_al[MM*CC];
__device__ __half        g_fh[MM*FF];
__device__ __nv_bfloat16 g_fl[MM*FF];
__device__ __half        g_wh[WELEMS];
__device__ __nv_bfloat16 g_wl[WELEMS];

__device__ __forceinline__ uint32_t smem_u32(const void* p) {
    uint32_t a;
    asm("{ .reg .u64 t; cvta.to.shared.u64 t, %1; cvt.u32.u64 %0, t; }" : "=r"(a) : "l"(p));
    return a;
}
__device__ __forceinline__ void ldsm4(uint32_t& r0, uint32_t& r1, uint32_t& r2, uint32_t& r3, uint32_t a) {
    asm volatile("ldmatrix.sync.aligned.m8n8.x4.shared.b16 {%0,%1,%2,%3},[%4];"
                 : "=r"(r0), "=r"(r1), "=r"(r2), "=r"(r3) : "r"(a));
}
__device__ __forceinline__ void mma_f16(float* c, const uint32_t* a, const uint32_t* b) {
    asm volatile(
        "mma.sync.aligned.m16n8k16.row.col.f32.f16.f16.f32 "
        "{%0,%1,%2,%3},{%4,%5,%6,%7},{%8,%9},{%0,%1,%2,%3};"
        : "+f"(c[0]), "+f"(c[1]), "+f"(c[2]), "+f"(c[3])
        : "r"(a[0]), "r"(a[1]), "r"(a[2]), "r"(a[3]), "r"(b[0]), "r"(b[1]));
}
__device__ __forceinline__ void mma_bf16(float* c, const uint32_t* a, const uint32_t* b) {
    asm volatile(
        "mma.sync.aligned.m16n8k16.row.col.f32.bf16.bf16.f32 "
        "{%0,%1,%2,%3},{%4,%5,%6,%7},{%8,%9},{%0,%1,%2,%3};"
        : "+f"(c[0]), "+f"(c[1]), "+f"(c[2]), "+f"(c[3])
        : "r"(a[0]), "r"(a[1]), "r"(a[2]), "r"(a[3]), "r"(b[0]), "r"(b[1]));
}
__device__ __forceinline__ void splitA1(float v, __half& h, __nv_bfloat16& l) {
    h = __float2half_rn(v);
    l = __float2bfloat16_rn(v - __half2float(h));
}
__device__ __forceinline__ void splitW1(float v, __half& h, __nv_bfloat16& l) {
    h = __float2half_rn(v);
    l = __float2bfloat16_rn(v);
}
__device__ __forceinline__ float gelu1(float v) {
    return 0.5f * v * (1.0f + erff(v * 0.70710678118654752f));
}
__device__ __forceinline__ unsigned long long pack2(float x, float y) {
    unsigned long long r;
    asm("mov.b64 %0, {%1, %2};" : "=l"(r) : "f"(x), "f"(y));
    return r;
}
__device__ __forceinline__ void fma2(unsigned long long& d, unsigned long long a, unsigned long long b) {
    asm("fma.rn.f32x2 %0, %1, %2, %0;" : "+l"(d) : "l"(a), "l"(b));
}
__device__ __forceinline__ void mul2(unsigned long long& d, unsigned long long a) {
    asm("mul.rn.f32x2 %0, %0, %1;" : "+l"(d) : "l"(a));
}
union U64F2 { unsigned long long u; float2 f; };

// 2-product GEMM: C = Ah*Bh (fp16 mma) + Al*Bb (bf16 mma) + bias
// MODE: 1=OUT_POS 2=QKV scatter 3=RESID 4=GELU_SPLIT
template<int MODE>
__global__ void __launch_bounds__(512, 1)
gemm_2p(const __half* __restrict__ Ah, const __nv_bfloat16* __restrict__ Al,
        const __half* __restrict__ Bh, const __nv_bfloat16* __restrict__ Bb,
        const float* __restrict__ bias, float* __restrict__ C,
        __half* __restrict__ oh, __nv_bfloat16* __restrict__ ol,
        const float* __restrict__ pos,
        float* __restrict__ qp, float* __restrict__ kp, float* __restrict__ vp,
        int Nn, int K)
{
    extern __shared__ unsigned char sm[];
    const uint32_t sbase = smem_u32(sm);
    const int tid = threadIdx.x, lane = tid & 31, wid = tid >> 5;
    const int wm = wid & 3, wn = wid >> 2;
    const int bm = blockIdx.y * 128, bn = blockIdx.x * 256;
    const int nc = K >> 5;

    auto load_stage = [&](int buf, int chunk) {
        const int k0 = chunk * 32;
        const uint32_t sb = sbase + buf * STAGE_SB;
        {
            int r = tid >> 2, seg = tid & 3;
            const __half* gA = Ah + (size_t)(bm + r) * K + k0 + seg * 8;
            uint32_t s = sb + r * ROWB + seg * 16;
            asm volatile("cp.async.cg.shared.global [%0], [%1], 16;" :: "r"(s), "l"(gA));
            const __nv_bfloat16* gA2 = Al + (size_t)(bm + r) * K + k0 + seg * 8;
            asm volatile("cp.async.cg.shared.global [%0], [%1], 16;" :: "r"(s + OFF_AL), "l"(gA2));
        }
#pragma unroll
        for (int j = 0; j < 2; j++) {
            int idx = tid + 512 * j;
            int r = idx >> 2, seg = idx & 3;
            const __half* gB = Bh + (size_t)(bn + r) * K + k0 + seg * 8;
            uint32_t s = sb + OFF_BH + r * ROWB + seg * 16;
            asm volatile("cp.async.cg.shared.global [%0], [%1], 16;" :: "r"(s), "l"(gB));
            const __nv_bfloat16* gB2 = Bb + (size_t)(bn + r) * K + k0 + seg * 8;
            asm volatile("cp.async.cg.shared.global [%0], [%1], 16;" :: "r"(s + 20480), "l"(gB2));
        }
        asm volatile("cp.async.commit_group;");
    };

    float acc[2][8][4] = {};

    load_stage(0, 0);
    load_stage(1, 1);
    asm volatile("cp.async.wait_group 1;");
    __syncthreads();

    const uint32_t brow = ((lane >> 4) << 3) + (lane & 7);
    for (int c = 0; c < nc; c++) {
        const uint32_t sb = sbase + (c & 1) * STAGE_SB;
#pragma unroll
        for (int k16 = 0; k16 < 2; k16++) {
            uint32_t bh[8][2], bl[8][2];
            const uint32_t bcol = k16 * 32 + ((lane >> 3) & 1) * 16;
#pragma unroll
            for (int ntp = 0; ntp < 4; ntp++) {
                uint32_t bd = sb + OFF_BH + (wn * 64 + ntp * 16 + brow) * ROWB + bcol;
                ldsm4(bh[2*ntp][0], bh[2*ntp][1], bh[2*ntp+1][0], bh[2*ntp+1][1], bd);
                ldsm4(bl[2*ntp][0], bl[2*ntp][1], bl[2*ntp+1][0], bl[2*ntp+1][1], bd + 20480);
            }
            const uint32_t acol = k16 * 32 + (lane >> 4) * 16;
#pragma unroll
            for (int mt = 0; mt < 2; mt++) {
                uint32_t ah4[4], al4[4];
                uint32_t ad = sb + (wm * 32 + mt * 16 + (lane & 15)) * ROWB + acol;
                ldsm4(ah4[0], ah4[1], ah4[2], ah4[3], ad);
                ldsm4(al4[0], al4[1], al4[2], al4[3], ad + OFF_AL);
#pragma unroll
                for (int nt = 0; nt < 8; nt++) mma_f16(acc[mt][nt], ah4, bh[nt]);
#pragma unroll
                for (int nt = 0; nt < 8; nt++) mma_bf16(acc[mt][nt], al4, bl[nt]);
            }
        }
        __syncthreads();
        if (c + 2 < nc) load_stage(c & 1, c + 2);
        asm volatile("cp.async.wait_group 1;");
        __syncthreads();
    }

    const int tr = lane >> 2, tc = (lane & 3) * 2;
#pragma unroll
    for (int mt = 0; mt < 2; mt++) {
        const int rb = bm + wm * 32 + mt * 16 + tr;
#pragma unroll
        for (int nt = 0; nt < 8; nt++) {
            const int c0 = bn + wn * 64 + nt * 8 + tc;
            const float b0 = bias[c0], b1 = bias[c0 + 1];
#pragma unroll
            for (int hrow = 0; hrow < 2; hrow++) {
                const int r = rb + hrow * 8;
                float v0 = acc[mt][nt][2 * hrow]     + b0;
                float v1 = acc[mt][nt][2 * hrow + 1] + b1;
                if (MODE == 1) {
                    const float2 pp = *reinterpret_cast<const float2*>(&pos[(size_t)(r & 511) * CC + c0]);
                    float2 o = { v0 + pp.x, v1 + pp.y };
                    *reinterpret_cast<float2*>(&C[(size_t)r * CC + c0]) = o;
                } else if (MODE == 2) {
                    const int which = c0 >> 10, ci = c0 & 1023;
                    const int head = ci >> 6, hd = ci & 63;
                    const int bb2 = r >> 9, n = r & 511;
                    const size_t off = ((size_t)(bb2 * HH + head) * NN + n) * HD + hd;
                    if (which == 0) {
                        float2 o = { v0 * 0.125f, v1 * 0.125f };
                        *reinterpret_cast<float2*>(&qp[off]) = o;
                    } else if (which == 1) {
                        float2 o = { v0, v1 };
                        *reinterpret_cast<float2*>(&kp[off]) = o;
                    } else {
                        float2 o = { v0, v1 };
                        *reinterpret_cast<float2*>(&vp[off]) = o;
                    }
                } else if (MODE == 3) {
                    float2* p = reinterpret_cast<float2*>(&C[(size_t)r * Nn + c0]);
                    float2 old = *p;
                    old.x += v0; old.y += v1;
                    *p = old;
                } else {
                    float gA = gelu1(v0), gB = gelu1(v1);
                    __half h0, h1; __nv_bfloat16 l0, l1;
                    splitA1(gA, h0, l0); splitA1(gB, h1, l1);
                    __half2 hh; hh.x = h0; hh.y = h1;
                    __nv_bfloat162 ll; ll.x = l0; ll.y = l1;
                    *reinterpret_cast<__half2*>(&oh[(size_t)r * Nn + c0]) = hh;
                    *reinterpret_cast<__nv_bfloat162*>(&ol[(size_t)r * Nn + c0]) = ll;
                }
            }
        }
    }
}

// ---- fused flash attention (f32x2) ----
__global__ void __launch_bounds__(256, 2)
flash_k(const float* __restrict__ q, const float* __restrict__ k, const float* __restrict__ v,
        const int* __restrict__ mask,
        __half* __restrict__ oh, __nv_bfloat16* __restrict__ ol)
{
    extern __shared__ float fs[];
    float* QsT = fs;
    float* KsT = fs + 64 * FLD;
    float* Vs  = fs + 2 * 64 * FLD;
    float* PsT = fs + 3 * 64 * FLD;
    __shared__ int msk[64];

    const int tid = threadIdx.x, tx = tid & 15, ty = tid >> 4;
    const int bh = blockIdx.y, b = bh >> 4, head = bh & 15;
    const int q0 = blockIdx.x * 64;
    const float* qbase = q + ((size_t)bh * NN + q0) * HD;
    const float* kbase = k + (size_t)bh * NN * HD;
    const float* vbase = v + (size_t)bh * NN * HD;

#pragma unroll
    for (int i = 0; i < 4; i++) {
        int idx = tid + 256 * i;
        int row = idx >> 4, c4 = (idx & 15) * 4;
        float4 qq = *reinterpret_cast<const float4*>(qbase + row * HD + c4);
        QsT[(c4 + 0) * FLD + row] = qq.x;
        QsT[(c4 + 1) * FLD + row] = qq.y;
        QsT[(c4 + 2) * FLD + row] = qq.z;
        QsT[(c4 + 3) * FLD + row] = qq.w;
    }

    unsigned long long O2[4][2] = {};
    float m[4] = {-3.0e38f, -3.0e38f, -3.0e38f, -3.0e38f};
    float l[4] = {};

    for (int kc = 0; kc < 8; kc++) {
        __syncthreads();
#pragma unroll
        for (int i = 0; i < 4; i++) {
            int idx = tid + 256 * i;
            int row = idx >> 4, c4 = (idx & 15) * 4;
            float4 kk4 = *reinterpret_cast<const float4*>(kbase + (size_t)(kc * 64 + row) * HD + c4);
            KsT[(c4 + 0) * FLD + row] = kk4.x;
            KsT[(c4 + 1) * FLD + row] = kk4.y;
            KsT[(c4 + 2) * FLD + row] = kk4.z;
            KsT[(c4 + 3) * FLD + row] = kk4.w;
            float4 vv4 = *reinterpret_cast<const float4*>(vbase + (size_t)(kc * 64 + row) * HD + c4);
            *reinterpret_cast<float4*>(Vs + row * FLD + c4) = vv4;
        }
        if (tid < 64) msk[tid] = mask[b * NN + kc * 64 + tid];
        __syncthreads();

        unsigned long long s2[4][2] = {};
        for (int kk = 0; kk < 64; kk++) {
            float4 q4 = *reinterpret_cast<float4*>(QsT + kk * FLD + 4 * ty);
            float4 k4 = *reinterpret_cast<float4*>(KsT + kk * FLD + 4 * tx);
            unsigned long long kp0 = pack2(k4.x, k4.y), kp1 = pack2(k4.z, k4.w);
            float qa[4] = {q4.x, q4.y, q4.z, q4.w};
#pragma unroll
            for (int i = 0; i < 4; i++) {
                unsigned long long qq = pack2(qa[i], qa[i]);
                fma2(s2[i][0], qq, kp0);
                fma2(s2[i][1], qq, kp1);
            }
        }
        float s[4][4];
#pragma unroll
        for (int i = 0; i < 4; i++) {
            U64F2 u0, u1; u0.u = s2[i][0]; u1.u = s2[i][1];
            s[i][0] = u0.f.x; s[i][1] = u0.f.y; s[i][2] = u1.f.x; s[i][3] = u1.f.y;
        }
#pragma unroll
        for (int j = 0; j < 4; j++)
            if (msk[4 * tx + j] == 0) { s[0][j] = -1e9f; s[1][j] = -1e9f; s[2][j] = -1e9f; s[3][j] = -1e9f; }

#pragma unroll
        for (int i = 0; i < 4; i++) {
            float cm = fmaxf(fmaxf(s[i][0], s[i][1]), fmaxf(s[i][2], s[i][3]));
#pragma unroll
            for (int o = 8; o > 0; o >>= 1) cm = fmaxf(cm, __shfl_xor_sync(0xffffffffu, cm, o));
            float mn = fmaxf(m[i], cm);
            float corr = exp2f((m[i] - mn) * LOG2E);
            m[i] = mn;
            float rs = 0.0f;
#pragma unroll
            for (int j = 0; j < 4; j++) { s[i][j] = exp2f((s[i][j] - mn) * LOG2E); rs += s[i][j]; }
#pragma unroll
            for (int o = 8; o > 0; o >>= 1) rs += __shfl_xor_sync(0xffffffffu, rs, o);
            l[i] = l[i] * corr + rs;
            unsigned long long cp = pack2(corr, corr);
            mul2(O2[i][0], cp);
            mul2(O2[i][1], cp);
        }
#pragma unroll
        for (int j = 0; j < 4; j++) {
            float4 pv = { s[0][j], s[1][j], s[2][j], s[3][j] };
            *reinterpret_cast<float4*>(PsT + (4 * tx + j) * FLD + 4 * ty) = pv;
        }
        __syncthreads();

        for (int kk = 0; kk < 64; kk++) {
            float4 p4 = *reinterpret_cast<float4*>(PsT + kk * FLD + 4 * ty);
            float4 v4 = *reinterpret_cast<float4*>(Vs + kk * FLD + 4 * tx);
            unsigned long long vp0 = pack2(v4.x, v4.y), vp1 = pack2(v4.z, v4.w);
            float pa[4] = {p4.x, p4.y, p4.z, p4.w};
#pragma unroll
            for (int i = 0; i < 4; i++) {
                unsigned long long pp = pack2(pa[i], pa[i]);
                fma2(O2[i][0], pp, vp0);
                fma2(O2[i][1], pp, vp1);
            }
        }
    }

#pragma unroll
    for (int i = 0; i < 4; i++) {
        float inv = 1.0f / l[i];
        U64F2 u0, u1; u0.u = O2[i][0]; u1.u = O2[i][1];
        float o0 = u0.f.x * inv, o1 = u0.f.y * inv, o2 = u1.f.x * inv, o3 = u1.f.y * inv;
        __half h0, h1, h2, h3; __nv_bfloat16 l0, l1, l2, l3;
        splitA1(o0, h0, l0); splitA1(o1, h1, l1); splitA1(o2, h2, l2); splitA1(o3, h3, l3);
        const size_t off = ((size_t)(b * NN + q0 + 4 * ty + i)) * CC + head * HD + 4 * tx;
        __half2 hA; hA.x = h0; hA.y = h1;
        __half2 hB; hB.x = h2; hB.y = h3;
        __nv_bfloat162 lA; lA.x = l0; lA.y = l1;
        __nv_bfloat162 lB; lB.x = l2; lB.y = l3;
        *reinterpret_cast<__half2*>(&oh[off])     = hA;
        *reinterpret_cast<__half2*>(&oh[off + 2]) = hB;
        *reinterpret_cast<__nv_bfloat162*>(&ol[off])     = lA;
        *reinterpret_cast<__nv_bfloat162*>(&ol[off + 2]) = lB;
    }
}

// ---- reductions / elementwise ----
template<bool MAXRED>
__device__ __forceinline__ float blockReduce(float val) {
    __shared__ float sh[32];
    __syncthreads();
#pragma unroll
    for (int o = 16; o > 0; o >>= 1) {
        float t = __shfl_xor_sync(0xffffffffu, val, o);
        val = MAXRED ? fmaxf(val, t) : val + t;
    }
    int w = threadIdx.x >> 5, ln = threadIdx.x & 31;
    if (ln == 0) sh[w] = val;
    __syncthreads();
    int nw = blockDim.x >> 5;
    if (threadIdx.x < 32) {
        val = (ln < nw) ? sh[ln] : (MAXRED ? -3.4e38f : 0.0f);
#pragma unroll
        for (int o = 16; o > 0; o >>= 1) {
            float t = __shfl_xor_sync(0xffffffffu, val, o);
            val = MAXRED ? fmaxf(val, t) : val + t;
        }
        if (ln == 0) sh[0] = val;
    }
    __syncthreads();
    return sh[0];
}

__global__ void layernorm_split_k(const float* __restrict__ x, const float* __restrict__ g,
                                  const float* __restrict__ b,
                                  __half* __restrict__ oh, __nv_bfloat16* __restrict__ ol)
{
    int row = blockIdx.x, tid = threadIdx.x;
    const float* xr = x + (size_t)row * CC;
    float4 vv = *reinterpret_cast<const float4*>(xr + tid * 4);
    float s = blockReduce<false>(vv.x + vv.y + vv.z + vv.w);
    float mu = s * (1.0f / CC);
    float d0 = vv.x - mu, d1 = vv.y - mu, d2 = vv.z - mu, d3 = vv.w - mu;
    float s2 = blockReduce<false>(d0*d0 + d1*d1 + d2*d2 + d3*d3);
    float inv = rsqrtf(s2 * (1.0f / CC) + 1e-6f);
    float4 gg = *reinterpret_cast<const float4*>(g + tid * 4);
    float4 bb = *reinterpret_cast<const float4*>(b + tid * 4);
    float r0 = d0 * inv * gg.x + bb.x;
    float r1 = d1 * inv * gg.y + bb.y;
    float r2 = d2 * inv * gg.z + bb.z;
    float r3 = d3 * inv * gg.w + bb.w;
    __half h0, h1, h2, h3; __nv_bfloat16 l0, l1, l2, l3;
    splitA1(r0, h0, l0); splitA1(r1, h1, l1); splitA1(r2, h2, l2); splitA1(r3, h3, l3);
    size_t off = (size_t)row * CC + tid * 4;
    __half2 hA; hA.x = h0; hA.y = h1;
    __half2 hB; hB.x = h2; hB.y = h3;
    __nv_bfloat162 lA; lA.x = l0; lA.y = l1;
    __nv_bfloat162 lB; lB.x = l2; lB.y = l3;
    *reinterpret_cast<__half2*>(&oh[off])     = hA;
    *reinterpret_cast<__half2*>(&oh[off + 2]) = hB;
    *reinterpret_cast<__nv_bfloat162*>(&ol[off])     = lA;
    *reinterpret_cast<__nv_bfloat162*>(&ol[off + 2]) = lB;
}

template<int W>
__global__ void split_k(const float4* __restrict__ s, __half2* __restrict__ h,
                        __nv_bfloat162* __restrict__ l, int n4) {
    int i = blockIdx.x * blockDim.x + threadIdx.x;
    if (i < n4) {
        float4 v = s[i];
        __half h0, h1, h2, h3; __nv_bfloat16 l0, l1, l2, l3;
        if (W) { splitW1(v.x, h0, l0); splitW1(v.y, h1, l1); splitW1(v.z, h2, l2); splitW1(v.w, h3, l3); }
        else   { splitA1(v.x, h0, l0); splitA1(v.y, h1, l1); splitA1(v.z, h2, l2); splitA1(v.w, h3, l3); }
        __half2 hA; hA.x = h0; hA.y = h1;
        __half2 hB; hB.x = h2; hB.y = h3;
        __nv_bfloat162 lA; lA.x = l0; lA.y = l1;
        __nv_bfloat162 lB; lB.x = l2; lB.y = l3;
        h[2 * i] = hA; h[2 * i + 1] = hB;
        l[2 * i] = lA; l[2 * i + 1] = lB;
    }
}

__global__ void final_k(const float* __restrict__ x, const float* __restrict__ Wout,
                        const float* __restrict__ bout, float* __restrict__ out) {
    int mrow = blockIdx.x, j = threadIdx.x >> 5, lane = threadIdx.x & 31;
    const float* xr = x + (size_t)mrow * CC;
    const float* w  = Wout + (size_t)j * CC;
    float s = 0.0f;
#pragma unroll
    for (int t = 0; t < CC / 32; t++) s += xr[lane + 32 * t] * w[lane + 32 * t];
#pragma unroll
    for (int o = 16; o > 0; o >>= 1) s += __shfl_xor_sync(0xffffffffu, s, o);
    if (lane == 0) out[mrow * OUTD + j] = 1.0f / (1.0f + expf(-(s + bout[j])));
}

// ---- host ----
static inline dim3 eg4(int total) { return dim3((total / 4 + 255) / 256); }

extern "C" void kernel_launch(void* const* d_in, const int* in_sizes, int n_in,
                              void* d_out, int out_size)
{
    (void)in_sizes; (void)n_in; (void)out_size;
    const float* inputs = (const float*)d_in[0];
    const int*   mask   = (const int*)  d_in[1];
    const float* pos    = (const float*)d_in[2];
    const float* Wi     = (const float*)d_in[3];
    const float* bi     = (const float*)d_in[4];
    const float* ln1_g  = (const float*)d_in[5];
    const float* ln1_b  = (const float*)d_in[6];
    const float* Wqkv   = (const float*)d_in[7];
    const float* bqkv   = (const float*)d_in[8];
    const float* Wo     = (const float*)d_in[9];
    const float* bo     = (const float*)d_in[10];
    const float* ln2_g  = (const float*)d_in[11];
    const float* ln2_b  = (const float*)d_in[12];
    const float* W1     = (const float*)d_in[13];
    const float* b1     = (const float*)d_in[14];
    const float* W2     = (const float*)d_in[15];
    const float* b2     = (const float*)d_in[16];
    const float* Wout   = (const float*)d_in[17];
    const float* bout   = (const float*)d_in[18];

    float *x, *q, *k, *v;
    __half *ah, *fh, *wh;
    __nv_bfloat16 *al, *fl, *wl;
    cudaGetSymbolAddress((void**)&x,  g_x);
    cudaGetSymbolAddress((void**)&q,  g_q);
    cudaGetSymbolAddress((void**)&k,  g_k);
    cudaGetSymbolAddress((void**)&v,  g_v);
    cudaGetSymbolAddress((void**)&ah, g_ah);
    cudaGetSymbolAddress((void**)&al, g_al);
    cudaGetSymbolAddress((void**)&fh, g_fh);
    cudaGetSymbolAddress((void**)&fl, g_fl);
    cudaGetSymbolAddress((void**)&wh, g_wh);
    cudaGetSymbolAddress((void**)&wl, g_wl);

    cudaFuncSetAttribute(gemm_2p<1>, cudaFuncAttributeMaxDynamicSharedMemorySize, DYN_SB);
    cudaFuncSetAttribute(gemm_2p<2>, cudaFuncAttributeMaxDynamicSharedMemorySize, DYN_SB);
    cudaFuncSetAttribute(gemm_2p<3>, cudaFuncAttributeMaxDynamicSharedMemorySize, DYN_SB);
    cudaFuncSetAttribute(gemm_2p<4>, cudaFuncAttributeMaxDynamicSharedMemorySize, DYN_SB);
    cudaFuncSetAttribute(flash_k, cudaFuncAttributeMaxDynamicSharedMemorySize, FLASH_SB);

    const int tot_xc = MM * CC;

    split_k<1><<<eg4(CC * CC), 256>>>((const float4*)Wi, (__half2*)(wh + OFF_WI),
                                      (__nv_bfloat162*)(wl + OFF_WI), CC * CC / 4);
    split_k<1><<<eg4(LL*3*CC*CC), 256>>>((const float4*)Wqkv, (__half2*)(wh + OFF_WQKV),
                                         (__nv_bfloat162*)(wl + OFF_WQKV), LL*3*CC*CC/4);
    split_k<1><<<eg4(LL*CC*CC), 256>>>((const float4*)Wo, (__half2*)(wh + OFF_WO),
                                       (__nv_bfloat162*)(wl + OFF_WO), LL*CC*CC/4);
    split_k<1><<<eg4(LL*FF*CC), 256>>>((const float4*)W1, (__half2*)(wh + OFF_W1),
                                       (__nv_bfloat162*)(wl + OFF_W1), LL*FF*CC/4);
    split_k<1><<<eg4(LL*CC*FF), 256>>>((const float4*)W2, (__half2*)(wh + OFF_W2),
                                       (__nv_bfloat162*)(wl + OFF_W2), LL*CC*FF/4);

    split_k<0><<<eg4(tot_xc), 256>>>((const float4*)inputs, (__half2*)ah,
                                     (__nv_bfloat162*)al, tot_xc / 4);
    gemm_2p<1><<<dim3(CC/256, MM/128), 512, DYN_SB>>>(
        ah, al, wh + OFF_WI, wl + OFF_WI, bi, x, nullptr, nullptr, pos,
        nullptr, nullptr, nullptr, CC, CC);

    for (int l = 0; l < LL; l++) {
        const size_t oq = OFF_WQKV + (size_t)l * 3 * CC * CC;
        const size_t oo = OFF_WO   + (size_t)l * CC * CC;
        const size_t o1 = OFF_W1   + (size_t)l * FF * CC;
        const size_t o2 = OFF_W2   + (size_t)l * CC * FF;

        layernorm_split_k<<<MM, 256>>>(x, ln1_g + l * CC, ln1_b + l * CC, ah, al);
        gemm_2p<2><<<dim3(3*CC/256, MM/128), 512, DYN_SB>>>(
            ah, al, wh + oq, wl + oq, bqkv + (size_t)l * 3 * CC, nullptr,
            nullptr, nullptr, nullptr, q, k, v, 3 * CC, CC);

        flash_k<<<dim3(NN/64, BHN), 256, FLASH_SB>>>(q, k, v, mask, ah, al);

        gemm_2p<3><<<dim3(CC/256, MM/128), 512, DYN_SB>>>(
            ah, al, wh + oo, wl + oo, bo + (size_t)l * CC, x,
            nullptr, nullptr, nullptr, nullptr, nullptr, nullptr, CC, CC);

        layernorm_split_k<<<MM, 256>>>(x, ln2_g + l * CC, ln2_b + l * CC, ah, al);
        gemm_2p<4><<<dim3(FF/256, MM/128), 512, DYN_SB>>>(
            ah, al, wh + o1, wl + o1, b1 + (size_t)l * FF, nullptr,
            fh, fl, nullptr, nullptr, nullptr, nullptr, FF, CC);
        gemm_2p<3><<<dim3(CC/256, MM/128), 512, DYN_SB>>>(
            fh, fl, wh + o2, wl + o2, b2 + (size_t)l * CC, x,
            nullptr, nullptr, nullptr, nullptr, nullptr, nullptr, CC, FF);
    }

    final_k<<<MM, 64>>>(x, Wout, bout, (float*)d_out);
}